// round 3
// baseline (speedup 1.0000x reference)
#include <cuda_runtime.h>
#include <math.h>

#define BB 4
#define SS 4096
#define DD 256
#define BQ 64
#define BK 64

// Scratch for projected q/k/v (device globals: allocation-free rule)
__device__ float g_q[BB*SS*DD];
__device__ float g_k[BB*SS*DD];
__device__ float g_v[BB*SS*DD];

// ---------------------------------------------------------------------------
// Kernel 1: QKV projection.  y[m][n] = sum_d x[m][d] * W[n][d] + b[n]
// M=16384, N=256, K=256.  64x64 output tile, 4x4 microtile, k-chunks of 64.
// blockIdx.z selects {q,k,v}.
// ---------------------------------------------------------------------------
__global__ __launch_bounds__(256) void qkv_kernel(
    const float* __restrict__ x,
    const float* __restrict__ Wq, const float* __restrict__ bq,
    const float* __restrict__ Wk, const float* __restrict__ bk,
    const float* __restrict__ Wv, const float* __restrict__ bv)
{
    const float* W;
    const float* bias;
    float* out;
    if (blockIdx.z == 0)      { W = Wq; bias = bq; out = g_q; }
    else if (blockIdx.z == 1) { W = Wk; bias = bk; out = g_k; }
    else                      { W = Wv; bias = bv; out = g_v; }

    __shared__ float Xs[64][68];
    __shared__ float Ws[64][68];

    const int tid = threadIdx.x;
    const int ty  = tid >> 4;     // 0..15 (row group)
    const int tx  = tid & 15;     // 0..15 (col group)
    const int m0  = blockIdx.x * 64;
    const int n0  = blockIdx.y * 64;

    float acc[4][4] = {};

    for (int kc = 0; kc < DD; kc += 64) {
        __syncthreads();
        // cooperative loads: 64 rows x 16 float4 each = 1024 float4 / 256 thr
        #pragma unroll
        for (int t = 0; t < 4; t++) {
            int idx = tid + t * 256;
            int row = idx >> 4, c4 = idx & 15;
            *(float4*)&Xs[row][c4*4] = *(const float4*)&x[(m0+row)*DD + kc + c4*4];
            *(float4*)&Ws[row][c4*4] = *(const float4*)&W[(n0+row)*DD + kc + c4*4];
        }
        __syncthreads();

        #pragma unroll 4
        for (int kk = 0; kk < 64; kk += 4) {
            float4 xv[4], wv[4];
            #pragma unroll
            for (int i = 0; i < 4; i++) xv[i] = *(const float4*)&Xs[ty*4+i][kk];
            #pragma unroll
            for (int c = 0; c < 4; c++) wv[c] = *(const float4*)&Ws[tx*4+c][kk];
            #pragma unroll
            for (int i = 0; i < 4; i++)
                #pragma unroll
                for (int c = 0; c < 4; c++)
                    acc[i][c] += xv[i].x*wv[c].x + xv[i].y*wv[c].y
                               + xv[i].z*wv[c].z + xv[i].w*wv[c].w;
        }
    }

    const float b0 = __ldg(&bias[n0 + tx*4 + 0]);
    const float b1 = __ldg(&bias[n0 + tx*4 + 1]);
    const float b2 = __ldg(&bias[n0 + tx*4 + 2]);
    const float b3 = __ldg(&bias[n0 + tx*4 + 3]);

    #pragma unroll
    for (int i = 0; i < 4; i++) {
        float4 o;
        o.x = acc[i][0] + b0;
        o.y = acc[i][1] + b1;
        o.z = acc[i][2] + b2;
        o.w = acc[i][3] + b3;
        *(float4*)&out[(m0 + ty*4 + i)*DD + n0 + tx*4] = o;
    }
}

// ---------------------------------------------------------------------------
// Kernel 2: flash attention, fp32.
// One block per (q-tile of 64 rows, batch).  256 threads.
// smem: Q[64][260] + K[64][260] + V[64][260] + P[64][68]  = 217,088 B
// Thread (ty,tx): S microtile rows ty*4..+3, cols tx*4..+3;
//                 O ownership rows ty*4..+3, cols {tx*4 + 64*kk, kk=0..3}
// ---------------------------------------------------------------------------
#define QKV_STRIDE 260
#define P_STRIDE   68
#define ATTN_SMEM_BYTES ((3*64*QKV_STRIDE + 64*P_STRIDE) * (int)sizeof(float))

__global__ __launch_bounds__(256, 1) void attn_kernel(float* __restrict__ out)
{
    extern __shared__ float sm[];
    float* Qs = sm;
    float* Ks = sm + 64*QKV_STRIDE;
    float* Vs = sm + 2*64*QKV_STRIDE;
    float* Ps = sm + 3*64*QKV_STRIDE;

    const int tid = threadIdx.x;
    const int ty  = tid >> 4;
    const int tx  = tid & 15;
    const int b   = blockIdx.y;
    const int q0  = blockIdx.x * BQ;

    const float* qg = g_q + (b*SS + q0)*DD;
    const float* kg = g_k + (size_t)b*SS*DD;
    const float* vg = g_v + (size_t)b*SS*DD;

    // Load Q tile: 64 rows x 64 float4 = 4096 float4 / 256 threads
    #pragma unroll
    for (int t = 0; t < 16; t++) {
        int idx = tid + t*256;
        int row = idx >> 6, c4 = idx & 63;
        *(float4*)&Qs[row*QKV_STRIDE + c4*4] = *(const float4*)&qg[row*DD + c4*4];
    }

    float m_i[4], l_i[4], Oacc[4][16];
    #pragma unroll
    for (int i = 0; i < 4; i++) {
        m_i[i] = -INFINITY;
        l_i[i] = 0.f;
        #pragma unroll
        for (int c = 0; c < 16; c++) Oacc[i][c] = 0.f;
    }

    const float scale = 0.0625f;   // 1/sqrt(256)

    for (int jt = 0; jt < SS; jt += BK) {
        __syncthreads();   // previous PV reads of Ks/Vs/Ps done (also orders Q load)
        #pragma unroll
        for (int t = 0; t < 16; t++) {
            int idx = tid + t*256;
            int row = idx >> 6, c4 = idx & 63;
            *(float4*)&Ks[row*QKV_STRIDE + c4*4] = *(const float4*)&kg[(jt+row)*DD + c4*4];
            *(float4*)&Vs[row*QKV_STRIDE + c4*4] = *(const float4*)&vg[(jt+row)*DD + c4*4];
        }
        __syncthreads();

        // ---- S = (Q K^T) * scale, 4x4 per thread, d vectorized by float4 ----
        float s[4][4] = {};
        #pragma unroll 2
        for (int d = 0; d < DD; d += 4) {
            float4 qv[4], kv[4];
            #pragma unroll
            for (int i = 0; i < 4; i++) qv[i] = *(const float4*)&Qs[(ty*4+i)*QKV_STRIDE + d];
            #pragma unroll
            for (int c = 0; c < 4; c++) kv[c] = *(const float4*)&Ks[(tx*4+c)*QKV_STRIDE + d];
            #pragma unroll
            for (int i = 0; i < 4; i++)
                #pragma unroll
                for (int c = 0; c < 4; c++)
                    s[i][c] += qv[i].x*kv[c].x + qv[i].y*kv[c].y
                             + qv[i].z*kv[c].z + qv[i].w*kv[c].w;
        }

        // ---- online softmax (per row; reduction over 16 tx lanes) ----
        #pragma unroll
        for (int i = 0; i < 4; i++) {
            #pragma unroll
            for (int c = 0; c < 4; c++) s[i][c] *= scale;

            float mx = fmaxf(fmaxf(s[i][0], s[i][1]), fmaxf(s[i][2], s[i][3]));
            #pragma unroll
            for (int off = 8; off; off >>= 1)
                mx = fmaxf(mx, __shfl_xor_sync(0xffffffffu, mx, off, 16));

            float mnew = fmaxf(m_i[i], mx);
            float p0 = __expf(s[i][0] - mnew);
            float p1 = __expf(s[i][1] - mnew);
            float p2 = __expf(s[i][2] - mnew);
            float p3 = __expf(s[i][3] - mnew);
            float rs = p0 + p1 + p2 + p3;
            #pragma unroll
            for (int off = 8; off; off >>= 1)
                rs += __shfl_xor_sync(0xffffffffu, rs, off, 16);

            float alpha = __expf(m_i[i] - mnew);   // -inf - finite -> 0 on first tile
            l_i[i] = l_i[i]*alpha + rs;
            m_i[i] = mnew;

            #pragma unroll
            for (int c = 0; c < 16; c++) Oacc[i][c] *= alpha;

            float4 pv = make_float4(p0, p1, p2, p3);
            *(float4*)&Ps[(ty*4+i)*P_STRIDE + tx*4] = pv;
        }
        __syncthreads();   // P visible to all columns

        // ---- O += P V ----
        #pragma unroll 2
        for (int j = 0; j < BK; j++) {
            float p[4];
            #pragma unroll
            for (int i = 0; i < 4; i++) p[i] = Ps[(ty*4+i)*P_STRIDE + j];   // broadcast
            #pragma unroll
            for (int kk = 0; kk < 4; kk++) {
                float4 vv = *(const float4*)&Vs[j*QKV_STRIDE + tx*4 + kk*64]; // conflict-free
                #pragma unroll
                for (int i = 0; i < 4; i++) {
                    Oacc[i][kk*4+0] += p[i]*vv.x;
                    Oacc[i][kk*4+1] += p[i]*vv.y;
                    Oacc[i][kk*4+2] += p[i]*vv.z;
                    Oacc[i][kk*4+3] += p[i]*vv.w;
                }
            }
        }
    }

    // ---- normalize + store ----
    #pragma unroll
    for (int i = 0; i < 4; i++) {
        float inv = 1.0f / l_i[i];
        int row = q0 + ty*4 + i;
        #pragma unroll
        for (int kk = 0; kk < 4; kk++) {
            float4 o;
            o.x = Oacc[i][kk*4+0] * inv;
            o.y = Oacc[i][kk*4+1] * inv;
            o.z = Oacc[i][kk*4+2] * inv;
            o.w = Oacc[i][kk*4+3] * inv;
            *(float4*)&out[((size_t)b*SS + row)*DD + tx*4 + kk*64] = o;
        }
    }
}

// ---------------------------------------------------------------------------
// Launch
// inputs: x, Wq, bq, Wk, bk, Wv, bv
// ---------------------------------------------------------------------------
extern "C" void kernel_launch(void* const* d_in, const int* in_sizes, int n_in,
                              void* d_out, int out_size)
{
    (void)in_sizes; (void)n_in; (void)out_size;
    const float* x  = (const float*)d_in[0];
    const float* Wq = (const float*)d_in[1];
    const float* bq = (const float*)d_in[2];
    const float* Wk = (const float*)d_in[3];
    const float* bk = (const float*)d_in[4];
    const float* Wv = (const float*)d_in[5];
    const float* bv = (const float*)d_in[6];
    float* out = (float*)d_out;

    dim3 grid_qkv((BB*SS)/64, DD/64, 3);
    qkv_kernel<<<grid_qkv, 256>>>(x, Wq, bq, Wk, bk, Wv, bv);

    cudaFuncSetAttribute(attn_kernel, cudaFuncAttributeMaxDynamicSharedMemorySize,
                         ATTN_SMEM_BYTES);
    dim3 grid_attn(SS/BQ, BB);
    attn_kernel<<<grid_attn, 256, ATTN_SMEM_BYTES>>>(out);
}

// round 4
// speedup vs baseline: 1.0017x; 1.0017x over previous
#include <cuda_runtime.h>
#include <math.h>

#define BB 4
#define SS 4096
#define DD 256
#define BQ 64
#define BK 64

// Scratch for projected q/k/v (device globals: allocation-free rule)
__device__ float g_q[BB*SS*DD];
__device__ float g_k[BB*SS*DD];
__device__ float g_v[BB*SS*DD];

// ---------------------------------------------------------------------------
// Kernel 1: QKV projection.  y[m][n] = sum_d x[m][d] * W[n][d] + b[n]
// M=16384, N=256, K=256.  64x64 output tile, 4x4 microtile, k-chunks of 64.
// blockIdx.z selects {q,k,v}.
// ---------------------------------------------------------------------------
__global__ __launch_bounds__(256) void qkv_kernel(
    const float* __restrict__ x,
    const float* __restrict__ Wq, const float* __restrict__ bq,
    const float* __restrict__ Wk, const float* __restrict__ bk,
    const float* __restrict__ Wv, const float* __restrict__ bv)
{
    const float* W;
    const float* bias;
    float* out;
    if (blockIdx.z == 0)      { W = Wq; bias = bq; out = g_q; }
    else if (blockIdx.z == 1) { W = Wk; bias = bk; out = g_k; }
    else                      { W = Wv; bias = bv; out = g_v; }

    __shared__ float Xs[64][68];
    __shared__ float Ws[64][68];

    const int tid = threadIdx.x;
    const int ty  = tid >> 4;     // 0..15 (row group)
    const int tx  = tid & 15;     // 0..15 (col group)
    const int m0  = blockIdx.x * 64;
    const int n0  = blockIdx.y * 64;

    float acc[4][4] = {};

    for (int kc = 0; kc < DD; kc += 64) {
        __syncthreads();
        // cooperative loads: 64 rows x 16 float4 each = 1024 float4 / 256 thr
        #pragma unroll
        for (int t = 0; t < 4; t++) {
            int idx = tid + t * 256;
            int row = idx >> 4, c4 = idx & 15;
            *(float4*)&Xs[row][c4*4] = *(const float4*)&x[(m0+row)*DD + kc + c4*4];
            *(float4*)&Ws[row][c4*4] = *(const float4*)&W[(n0+row)*DD + kc + c4*4];
        }
        __syncthreads();

        #pragma unroll 4
        for (int kk = 0; kk < 64; kk += 4) {
            float4 xv[4], wv[4];
            #pragma unroll
            for (int i = 0; i < 4; i++) xv[i] = *(const float4*)&Xs[ty*4+i][kk];
            #pragma unroll
            for (int c = 0; c < 4; c++) wv[c] = *(const float4*)&Ws[tx*4+c][kk];
            #pragma unroll
            for (int i = 0; i < 4; i++)
                #pragma unroll
                for (int c = 0; c < 4; c++)
                    acc[i][c] += xv[i].x*wv[c].x + xv[i].y*wv[c].y
                               + xv[i].z*wv[c].z + xv[i].w*wv[c].w;
        }
    }

    const float b0 = __ldg(&bias[n0 + tx*4 + 0]);
    const float b1 = __ldg(&bias[n0 + tx*4 + 1]);
    const float b2 = __ldg(&bias[n0 + tx*4 + 2]);
    const float b3 = __ldg(&bias[n0 + tx*4 + 3]);

    #pragma unroll
    for (int i = 0; i < 4; i++) {
        float4 o;
        o.x = acc[i][0] + b0;
        o.y = acc[i][1] + b1;
        o.z = acc[i][2] + b2;
        o.w = acc[i][3] + b3;
        *(float4*)&out[(m0 + ty*4 + i)*DD + n0 + tx*4] = o;
    }
}

// ---------------------------------------------------------------------------
// Kernel 2: flash attention, fp32.
// One block per (q-tile of 64 rows, batch).  256 threads.
// smem: Q[64][260] + K[64][260] + V[64][260] + P[64][68]  = 217,088 B
// Thread (ty,tx): S microtile rows ty*4..+3, cols tx*4..+3;
//                 O ownership rows ty*4..+3, cols {tx*4 + 64*kk, kk=0..3}
// ---------------------------------------------------------------------------
#define QKV_STRIDE 260
#define P_STRIDE   68
#define ATTN_SMEM_BYTES ((3*64*QKV_STRIDE + 64*P_STRIDE) * (int)sizeof(float))

__global__ __launch_bounds__(256, 1) void attn_kernel(float* __restrict__ out)
{
    extern __shared__ float sm[];
    float* Qs = sm;
    float* Ks = sm + 64*QKV_STRIDE;
    float* Vs = sm + 2*64*QKV_STRIDE;
    float* Ps = sm + 3*64*QKV_STRIDE;

    const int tid = threadIdx.x;
    const int ty  = tid >> 4;
    const int tx  = tid & 15;
    const int b   = blockIdx.y;
    const int q0  = blockIdx.x * BQ;

    const float* qg = g_q + (b*SS + q0)*DD;
    const float* kg = g_k + (size_t)b*SS*DD;
    const float* vg = g_v + (size_t)b*SS*DD;

    // Load Q tile: 64 rows x 64 float4 = 4096 float4 / 256 threads
    #pragma unroll
    for (int t = 0; t < 16; t++) {
        int idx = tid + t*256;
        int row = idx >> 6, c4 = idx & 63;
        *(float4*)&Qs[row*QKV_STRIDE + c4*4] = *(const float4*)&qg[row*DD + c4*4];
    }

    float m_i[4], l_i[4], Oacc[4][16];
    #pragma unroll
    for (int i = 0; i < 4; i++) {
        m_i[i] = -INFINITY;
        l_i[i] = 0.f;
        #pragma unroll
        for (int c = 0; c < 16; c++) Oacc[i][c] = 0.f;
    }

    const float scale = 0.0625f;   // 1/sqrt(256)

    for (int jt = 0; jt < SS; jt += BK) {
        __syncthreads();   // previous PV reads of Ks/Vs/Ps done (also orders Q load)
        #pragma unroll
        for (int t = 0; t < 16; t++) {
            int idx = tid + t*256;
            int row = idx >> 6, c4 = idx & 63;
            *(float4*)&Ks[row*QKV_STRIDE + c4*4] = *(const float4*)&kg[(jt+row)*DD + c4*4];
            *(float4*)&Vs[row*QKV_STRIDE + c4*4] = *(const float4*)&vg[(jt+row)*DD + c4*4];
        }
        __syncthreads();

        // ---- S = (Q K^T) * scale, 4x4 per thread, d vectorized by float4 ----
        float s[4][4] = {};
        #pragma unroll 2
        for (int d = 0; d < DD; d += 4) {
            float4 qv[4], kv[4];
            #pragma unroll
            for (int i = 0; i < 4; i++) qv[i] = *(const float4*)&Qs[(ty*4+i)*QKV_STRIDE + d];
            #pragma unroll
            for (int c = 0; c < 4; c++) kv[c] = *(const float4*)&Ks[(tx*4+c)*QKV_STRIDE + d];
            #pragma unroll
            for (int i = 0; i < 4; i++)
                #pragma unroll
                for (int c = 0; c < 4; c++)
                    s[i][c] += qv[i].x*kv[c].x + qv[i].y*kv[c].y
                             + qv[i].z*kv[c].z + qv[i].w*kv[c].w;
        }

        // ---- online softmax (per row; reduction over 16 tx lanes) ----
        #pragma unroll
        for (int i = 0; i < 4; i++) {
            #pragma unroll
            for (int c = 0; c < 4; c++) s[i][c] *= scale;

            float mx = fmaxf(fmaxf(s[i][0], s[i][1]), fmaxf(s[i][2], s[i][3]));
            #pragma unroll
            for (int off = 8; off; off >>= 1)
                mx = fmaxf(mx, __shfl_xor_sync(0xffffffffu, mx, off, 16));

            float mnew = fmaxf(m_i[i], mx);
            float p0 = __expf(s[i][0] - mnew);
            float p1 = __expf(s[i][1] - mnew);
            float p2 = __expf(s[i][2] - mnew);
            float p3 = __expf(s[i][3] - mnew);
            float rs = p0 + p1 + p2 + p3;
            #pragma unroll
            for (int off = 8; off; off >>= 1)
                rs += __shfl_xor_sync(0xffffffffu, rs, off, 16);

            float alpha = __expf(m_i[i] - mnew);   // -inf - finite -> 0 on first tile
            l_i[i] = l_i[i]*alpha + rs;
            m_i[i] = mnew;

            #pragma unroll
            for (int c = 0; c < 16; c++) Oacc[i][c] *= alpha;

            float4 pv = make_float4(p0, p1, p2, p3);
            *(float4*)&Ps[(ty*4+i)*P_STRIDE + tx*4] = pv;
        }
        __syncthreads();   // P visible to all columns

        // ---- O += P V ----
        #pragma unroll 2
        for (int j = 0; j < BK; j++) {
            float p[4];
            #pragma unroll
            for (int i = 0; i < 4; i++) p[i] = Ps[(ty*4+i)*P_STRIDE + j];   // broadcast
            #pragma unroll
            for (int kk = 0; kk < 4; kk++) {
                float4 vv = *(const float4*)&Vs[j*QKV_STRIDE + tx*4 + kk*64]; // conflict-free
                #pragma unroll
                for (int i = 0; i < 4; i++) {
                    Oacc[i][kk*4+0] += p[i]*vv.x;
                    Oacc[i][kk*4+1] += p[i]*vv.y;
                    Oacc[i][kk*4+2] += p[i]*vv.z;
                    Oacc[i][kk*4+3] += p[i]*vv.w;
                }
            }
        }
    }

    // ---- normalize + store ----
    #pragma unroll
    for (int i = 0; i < 4; i++) {
        float inv = 1.0f / l_i[i];
        int row = q0 + ty*4 + i;
        #pragma unroll
        for (int kk = 0; kk < 4; kk++) {
            float4 o;
            o.x = Oacc[i][kk*4+0] * inv;
            o.y = Oacc[i][kk*4+1] * inv;
            o.z = Oacc[i][kk*4+2] * inv;
            o.w = Oacc[i][kk*4+3] * inv;
            *(float4*)&out[((size_t)b*SS + row)*DD + tx*4 + kk*64] = o;
        }
    }
}

// ---------------------------------------------------------------------------
// Launch
// inputs: x, Wq, bq, Wk, bk, Wv, bv
// ---------------------------------------------------------------------------
extern "C" void kernel_launch(void* const* d_in, const int* in_sizes, int n_in,
                              void* d_out, int out_size)
{
    (void)in_sizes; (void)n_in; (void)out_size;
    const float* x  = (const float*)d_in[0];
    const float* Wq = (const float*)d_in[1];
    const float* bq = (const float*)d_in[2];
    const float* Wk = (const float*)d_in[3];
    const float* bk = (const float*)d_in[4];
    const float* Wv = (const float*)d_in[5];
    const float* bv = (const float*)d_in[6];
    float* out = (float*)d_out;

    dim3 grid_qkv((BB*SS)/64, DD/64, 3);
    qkv_kernel<<<grid_qkv, 256>>>(x, Wq, bq, Wk, bk, Wv, bv);

    cudaFuncSetAttribute(attn_kernel, cudaFuncAttributeMaxDynamicSharedMemorySize,
                         ATTN_SMEM_BYTES);
    dim3 grid_attn(SS/BQ, BB);
    attn_kernel<<<grid_attn, 256, ATTN_SMEM_BYTES>>>(out);
}

// round 5
// speedup vs baseline: 2.5945x; 2.5900x over previous
#include <cuda_runtime.h>
#include <cuda_bf16.h>
#include <math.h>

#define BB 4
#define SS 4096
#define DD 256
#define BQ 64
#define BK 64

// Scratch for projected q/k/v (device globals: allocation-free rule)
__device__ float g_q[BB*SS*DD];
__device__ float g_k[BB*SS*DD];
__device__ float g_v[BB*SS*DD];

// ---------------------------------------------------------------------------
// Kernel 1: QKV projection (unchanged from R3 — ~330us, revisit later).
// ---------------------------------------------------------------------------
__global__ __launch_bounds__(256) void qkv_kernel(
    const float* __restrict__ x,
    const float* __restrict__ Wq, const float* __restrict__ bq,
    const float* __restrict__ Wk, const float* __restrict__ bk,
    const float* __restrict__ Wv, const float* __restrict__ bv)
{
    const float* W;
    const float* bias;
    float* out;
    if (blockIdx.z == 0)      { W = Wq; bias = bq; out = g_q; }
    else if (blockIdx.z == 1) { W = Wk; bias = bk; out = g_k; }
    else                      { W = Wv; bias = bv; out = g_v; }

    __shared__ float Xs[64][68];
    __shared__ float Ws[64][68];

    const int tid = threadIdx.x;
    const int ty  = tid >> 4;
    const int tx  = tid & 15;
    const int m0  = blockIdx.x * 64;
    const int n0  = blockIdx.y * 64;

    float acc[4][4] = {};

    for (int kc = 0; kc < DD; kc += 64) {
        __syncthreads();
        #pragma unroll
        for (int t = 0; t < 4; t++) {
            int idx = tid + t * 256;
            int row = idx >> 4, c4 = idx & 15;
            *(float4*)&Xs[row][c4*4] = *(const float4*)&x[(m0+row)*DD + kc + c4*4];
            *(float4*)&Ws[row][c4*4] = *(const float4*)&W[(n0+row)*DD + kc + c4*4];
        }
        __syncthreads();

        #pragma unroll 4
        for (int kk = 0; kk < 64; kk += 4) {
            float4 xv[4], wv[4];
            #pragma unroll
            for (int i = 0; i < 4; i++) xv[i] = *(const float4*)&Xs[ty*4+i][kk];
            #pragma unroll
            for (int c = 0; c < 4; c++) wv[c] = *(const float4*)&Ws[tx*4+c][kk];
            #pragma unroll
            for (int i = 0; i < 4; i++)
                #pragma unroll
                for (int c = 0; c < 4; c++)
                    acc[i][c] += xv[i].x*wv[c].x + xv[i].y*wv[c].y
                               + xv[i].z*wv[c].z + xv[i].w*wv[c].w;
        }
    }

    const float b0 = __ldg(&bias[n0 + tx*4 + 0]);
    const float b1 = __ldg(&bias[n0 + tx*4 + 1]);
    const float b2 = __ldg(&bias[n0 + tx*4 + 2]);
    const float b3 = __ldg(&bias[n0 + tx*4 + 3]);

    #pragma unroll
    for (int i = 0; i < 4; i++) {
        float4 o;
        o.x = acc[i][0] + b0;
        o.y = acc[i][1] + b1;
        o.z = acc[i][2] + b2;
        o.w = acc[i][3] + b3;
        *(float4*)&out[(m0 + ty*4 + i)*DD + n0 + tx*4] = o;
    }
}

// ---------------------------------------------------------------------------
// Kernel 2: flash attention on tensor cores (mma.sync m16n8k16 bf16,
// split-bf16 3-MMA for fp32-class accuracy).
//
// Block = 256 threads = 8 warps in a 4(row) x 2(col) grid.
// Per block: Q tile 64x256 (resident), loop over 64-key tiles.
//   S-phase : warp computes 16x32 of S(64x64); 4 n-frags, 16 k-steps.
//   PV-phase: warp computes 16x128 of O(64x256); 16 n-frags, 4 k-steps.
// V is stored transposed in smem so B-fragment k-pairs are contiguous.
// All frag LDS patterns are bank-conflict-free by padding (stride%32 == 4 wds).
// ---------------------------------------------------------------------------
#define QSTR 264   // bf16 elems per Q/K row (256 + 8 pad)
#define VSTR 72    // bf16 elems per Vt row (64 keys + 8 pad)
#define PSTR 72    // bf16 elems per P row  (64 + 8 pad)

// bytes: Q 2*33792 + K 2*33792 + Vt 2*36864 + P 2*9216 + red 1024
#define ATTN_SMEM_BYTES 228352

__device__ __forceinline__ void mma16816(float& d0, float& d1, float& d2, float& d3,
                                         unsigned a0, unsigned a1, unsigned a2, unsigned a3,
                                         unsigned b0, unsigned b1)
{
    asm volatile(
        "mma.sync.aligned.m16n8k16.row.col.f32.bf16.bf16.f32 "
        "{%0,%1,%2,%3}, {%4,%5,%6,%7}, {%8,%9}, {%0,%1,%2,%3};\n"
        : "+f"(d0), "+f"(d1), "+f"(d2), "+f"(d3)
        : "r"(a0), "r"(a1), "r"(a2), "r"(a3), "r"(b0), "r"(b1));
}

// Split two floats into packed bf16 (hi) and packed bf16 residual (lo).
__device__ __forceinline__ void split_pair(float x, float y, unsigned& hi, unsigned& lo)
{
    __nv_bfloat16 xh = __float2bfloat16_rn(x);
    __nv_bfloat16 yh = __float2bfloat16_rn(y);
    __nv_bfloat162 h; h.x = xh; h.y = yh;
    __nv_bfloat162 l;
    l.x = __float2bfloat16_rn(x - __bfloat162float(xh));
    l.y = __float2bfloat16_rn(y - __bfloat162float(yh));
    hi = reinterpret_cast<unsigned&>(h);
    lo = reinterpret_cast<unsigned&>(l);
}

__global__ __launch_bounds__(256, 1) void attn_kernel(float* __restrict__ out)
{
    extern __shared__ char smbase[];
    __nv_bfloat16* Qh  = (__nv_bfloat16*)smbase;
    __nv_bfloat16* Ql  = Qh  + 64*QSTR;
    __nv_bfloat16* Kh  = Ql  + 64*QSTR;
    __nv_bfloat16* Kl  = Kh  + 64*QSTR;
    __nv_bfloat16* Vth = Kl  + 64*QSTR;
    __nv_bfloat16* Vtl = Vth + 256*VSTR;
    __nv_bfloat16* Ph  = Vtl + 256*VSTR;
    __nv_bfloat16* Pl  = Ph  + 64*PSTR;
    float* redm = (float*)(Pl + 64*PSTR);   // [2][64]
    float* reds = redm + 128;               // [2][64]

    const int tid  = threadIdx.x;
    const int lane = tid & 31;
    const int w    = tid >> 5;
    const int g    = lane >> 2;     // 0..7
    const int c    = lane & 3;      // 0..3
    const int wr   = w >> 1;        // 0..3
    const int wc   = w & 1;         // 0..1
    const int b    = blockIdx.y;
    const int q0   = blockIdx.x * BQ;
    const int r0   = wr*16 + g;     // S/O row 0 this thread owns
    const int r1   = r0 + 8;        // S/O row 1

    const float* qg = g_q + ((size_t)b*SS + q0)*DD;
    const float* kg = g_k + (size_t)b*SS*DD;
    const float* vg = g_v + (size_t)b*SS*DD;

    // ---- load Q tile once, pre-scaled by 1/sqrt(D) = 2^-4 (exact) ----
    #pragma unroll
    for (int t = 0; t < 16; t++) {
        int idx = tid + t*256;
        int row = idx >> 6, c4 = idx & 63;
        float4 f = *(const float4*)&qg[row*DD + c4*4];
        f.x *= 0.0625f; f.y *= 0.0625f; f.z *= 0.0625f; f.w *= 0.0625f;
        unsigned h0, l0, h1, l1;
        split_pair(f.x, f.y, h0, l0);
        split_pair(f.z, f.w, h1, l1);
        unsigned* ph = (unsigned*)&Qh[row*QSTR + c4*4];
        unsigned* pl = (unsigned*)&Ql[row*QSTR + c4*4];
        ph[0] = h0; ph[1] = h1;
        pl[0] = l0; pl[1] = l1;
    }

    float m0 = -INFINITY, m1 = -INFINITY, lsum0 = 0.f, lsum1 = 0.f;
    float O[16][4];
    #pragma unroll
    for (int nf = 0; nf < 16; nf++)
        #pragma unroll
        for (int r = 0; r < 4; r++) O[nf][r] = 0.f;

    for (int jt = 0; jt < SS; jt += BK) {
        __syncthreads();   // previous iter's S/PV reads of K/Vt/P are done

        // ---- load K tile [64][256] -> Kh/Kl ----
        #pragma unroll
        for (int t = 0; t < 16; t++) {
            int idx = tid + t*256;
            int row = idx >> 6, c4 = idx & 63;
            float4 f = *(const float4*)&kg[(jt+row)*DD + c4*4];
            unsigned h0, l0, h1, l1;
            split_pair(f.x, f.y, h0, l0);
            split_pair(f.z, f.w, h1, l1);
            unsigned* ph = (unsigned*)&Kh[row*QSTR + c4*4];
            unsigned* pl = (unsigned*)&Kl[row*QSTR + c4*4];
            ph[0] = h0; ph[1] = h1;
            pl[0] = l0; pl[1] = l1;
        }
        // ---- load V tile [64][256] transposed -> Vth/Vtl [256][72] ----
        #pragma unroll
        for (int t = 0; t < 16; t++) {
            int idx = tid + t*256;
            int key = idx & 63, c4 = idx >> 6;
            float4 f = *(const float4*)&vg[(jt+key)*DD + c4*4];
            float vals[4] = {f.x, f.y, f.z, f.w};
            #pragma unroll
            for (int j = 0; j < 4; j++) {
                __nv_bfloat16 h = __float2bfloat16_rn(vals[j]);
                Vth[(c4*4 + j)*VSTR + key] = h;
                Vtl[(c4*4 + j)*VSTR + key] =
                    __float2bfloat16_rn(vals[j] - __bfloat162float(h));
            }
        }
        __syncthreads();

        // ---- S = Q K^T  (warp tile 16x32), split-bf16 3-MMA ----
        float S[4][4];
        #pragma unroll
        for (int nf = 0; nf < 4; nf++)
            #pragma unroll
            for (int r = 0; r < 4; r++) S[nf][r] = 0.f;

        const int arow = wr*16;
        #pragma unroll 4
        for (int ks = 0; ks < 16; ks++) {
            const int k0 = ks*16;
            unsigned ah0 = *(unsigned*)&Qh[(arow+g  )*QSTR + k0 + 2*c];
            unsigned ah1 = *(unsigned*)&Qh[(arow+g+8)*QSTR + k0 + 2*c];
            unsigned ah2 = *(unsigned*)&Qh[(arow+g  )*QSTR + k0 + 8 + 2*c];
            unsigned ah3 = *(unsigned*)&Qh[(arow+g+8)*QSTR + k0 + 8 + 2*c];
            unsigned al0 = *(unsigned*)&Ql[(arow+g  )*QSTR + k0 + 2*c];
            unsigned al1 = *(unsigned*)&Ql[(arow+g+8)*QSTR + k0 + 2*c];
            unsigned al2 = *(unsigned*)&Ql[(arow+g  )*QSTR + k0 + 8 + 2*c];
            unsigned al3 = *(unsigned*)&Ql[(arow+g+8)*QSTR + k0 + 8 + 2*c];
            #pragma unroll
            for (int nf = 0; nf < 4; nf++) {
                const int n0 = wc*32 + nf*8;
                unsigned bh0 = *(unsigned*)&Kh[(n0+g)*QSTR + k0 + 2*c];
                unsigned bh1 = *(unsigned*)&Kh[(n0+g)*QSTR + k0 + 8 + 2*c];
                unsigned bl0 = *(unsigned*)&Kl[(n0+g)*QSTR + k0 + 2*c];
                unsigned bl1 = *(unsigned*)&Kl[(n0+g)*QSTR + k0 + 8 + 2*c];
                mma16816(S[nf][0], S[nf][1], S[nf][2], S[nf][3],
                         ah0, ah1, ah2, ah3, bh0, bh1);   // hi*hi
                mma16816(S[nf][0], S[nf][1], S[nf][2], S[nf][3],
                         al0, al1, al2, al3, bh0, bh1);   // lo*hi
                mma16816(S[nf][0], S[nf][1], S[nf][2], S[nf][3],
                         ah0, ah1, ah2, ah3, bl0, bl1);   // hi*lo
            }
        }

        // ---- online softmax: warp-local row max, then cross-warp via smem ----
        float rm0 = -INFINITY, rm1 = -INFINITY;
        #pragma unroll
        for (int nf = 0; nf < 4; nf++) {
            rm0 = fmaxf(rm0, fmaxf(S[nf][0], S[nf][1]));
            rm1 = fmaxf(rm1, fmaxf(S[nf][2], S[nf][3]));
        }
        rm0 = fmaxf(rm0, __shfl_xor_sync(0xffffffffu, rm0, 1));
        rm0 = fmaxf(rm0, __shfl_xor_sync(0xffffffffu, rm0, 2));
        rm1 = fmaxf(rm1, __shfl_xor_sync(0xffffffffu, rm1, 1));
        rm1 = fmaxf(rm1, __shfl_xor_sync(0xffffffffu, rm1, 2));
        if (c == 0) {
            redm[wc*64 + r0] = rm0;
            redm[wc*64 + r1] = rm1;
        }
        __syncthreads();

        float mn0 = fmaxf(m0, fmaxf(redm[r0], redm[64 + r0]));
        float mn1 = fmaxf(m1, fmaxf(redm[r1], redm[64 + r1]));

        float ps0 = 0.f, ps1 = 0.f;
        #pragma unroll
        for (int nf = 0; nf < 4; nf++) {
            float p0 = __expf(S[nf][0] - mn0);
            float p1 = __expf(S[nf][1] - mn0);
            float p2 = __expf(S[nf][2] - mn1);
            float p3 = __expf(S[nf][3] - mn1);
            ps0 += p0 + p1;
            ps1 += p2 + p3;
            const int col = wc*32 + nf*8 + 2*c;
            unsigned hi, lo;
            split_pair(p0, p1, hi, lo);
            *(unsigned*)&Ph[r0*PSTR + col] = hi;
            *(unsigned*)&Pl[r0*PSTR + col] = lo;
            split_pair(p2, p3, hi, lo);
            *(unsigned*)&Ph[r1*PSTR + col] = hi;
            *(unsigned*)&Pl[r1*PSTR + col] = lo;
        }
        ps0 += __shfl_xor_sync(0xffffffffu, ps0, 1);
        ps0 += __shfl_xor_sync(0xffffffffu, ps0, 2);
        ps1 += __shfl_xor_sync(0xffffffffu, ps1, 1);
        ps1 += __shfl_xor_sync(0xffffffffu, ps1, 2);
        if (c == 0) {
            reds[wc*64 + r0] = ps0;
            reds[wc*64 + r1] = ps1;
        }
        __syncthreads();   // reds + P tiles visible

        float a0f = __expf(m0 - mn0);   // 0 on first tile (-inf - finite)
        float a1f = __expf(m1 - mn1);
        lsum0 = lsum0*a0f + reds[r0] + reds[64 + r0];
        lsum1 = lsum1*a1f + reds[r1] + reds[64 + r1];
        m0 = mn0; m1 = mn1;
        #pragma unroll
        for (int nf = 0; nf < 16; nf++) {
            O[nf][0] *= a0f; O[nf][1] *= a0f;
            O[nf][2] *= a1f; O[nf][3] *= a1f;
        }

        // ---- O += P V  (warp tile 16x128), split-bf16 3-MMA ----
        #pragma unroll
        for (int kk = 0; kk < 4; kk++) {
            const int k0 = kk*16;
            unsigned ah0 = *(unsigned*)&Ph[r0*PSTR + k0 + 2*c];
            unsigned ah1 = *(unsigned*)&Ph[r1*PSTR + k0 + 2*c];
            unsigned ah2 = *(unsigned*)&Ph[r0*PSTR + k0 + 8 + 2*c];
            unsigned ah3 = *(unsigned*)&Ph[r1*PSTR + k0 + 8 + 2*c];
            unsigned al0 = *(unsigned*)&Pl[r0*PSTR + k0 + 2*c];
            unsigned al1 = *(unsigned*)&Pl[r1*PSTR + k0 + 2*c];
            unsigned al2 = *(unsigned*)&Pl[r0*PSTR + k0 + 8 + 2*c];
            unsigned al3 = *(unsigned*)&Pl[r1*PSTR + k0 + 8 + 2*c];
            #pragma unroll
            for (int nf = 0; nf < 16; nf++) {
                const int n0 = wc*128 + nf*8;
                unsigned bh0 = *(unsigned*)&Vth[(n0+g)*VSTR + k0 + 2*c];
                unsigned bh1 = *(unsigned*)&Vth[(n0+g)*VSTR + k0 + 8 + 2*c];
                unsigned bl0 = *(unsigned*)&Vtl[(n0+g)*VSTR + k0 + 2*c];
                unsigned bl1 = *(unsigned*)&Vtl[(n0+g)*VSTR + k0 + 8 + 2*c];
                mma16816(O[nf][0], O[nf][1], O[nf][2], O[nf][3],
                         ah0, ah1, ah2, ah3, bh0, bh1);   // hi*hi
                mma16816(O[nf][0], O[nf][1], O[nf][2], O[nf][3],
                         al0, al1, al2, al3, bh0, bh1);   // lo*hi
                mma16816(O[nf][0], O[nf][1], O[nf][2], O[nf][3],
                         ah0, ah1, ah2, ah3, bl0, bl1);   // hi*lo
            }
        }
    }

    // ---- normalize + store (float2 pairs, cols 2c/2c+1) ----
    const float inv0 = 1.0f / lsum0;
    const float inv1 = 1.0f / lsum1;
    #pragma unroll
    for (int nf = 0; nf < 16; nf++) {
        const int col = wc*128 + nf*8 + 2*c;
        float2 o0, o1;
        o0.x = O[nf][0]*inv0; o0.y = O[nf][1]*inv0;
        o1.x = O[nf][2]*inv1; o1.y = O[nf][3]*inv1;
        *(float2*)&out[((size_t)b*SS + q0 + r0)*DD + col] = o0;
        *(float2*)&out[((size_t)b*SS + q0 + r1)*DD + col] = o1;
    }
}

// ---------------------------------------------------------------------------
// Launch
// ---------------------------------------------------------------------------
extern "C" void kernel_launch(void* const* d_in, const int* in_sizes, int n_in,
                              void* d_out, int out_size)
{
    (void)in_sizes; (void)n_in; (void)out_size;
    const float* x  = (const float*)d_in[0];
    const float* Wq = (const float*)d_in[1];
    const float* bq = (const float*)d_in[2];
    const float* Wk = (const float*)d_in[3];
    const float* bk = (const float*)d_in[4];
    const float* Wv = (const float*)d_in[5];
    const float* bv = (const float*)d_in[6];
    float* out = (float*)d_out;

    dim3 grid_qkv((BB*SS)/64, DD/64, 3);
    qkv_kernel<<<grid_qkv, 256>>>(x, Wq, bq, Wk, bk, Wv, bv);

    cudaFuncSetAttribute(attn_kernel, cudaFuncAttributeMaxDynamicSharedMemorySize,
                         ATTN_SMEM_BYTES);
    dim3 grid_attn(SS/BQ, BB);
    attn_kernel<<<grid_attn, 256, ATTN_SMEM_BYTES>>>(out);
}

// round 6
// speedup vs baseline: 3.1371x; 1.2091x over previous
#include <cuda_runtime.h>
#include <cuda_fp16.h>
#include <math.h>

#define BB 4
#define SS 4096
#define DD 256
#define BQ 64
#define BK 64

// fp16 hi/lo split projections (written by qkv_kernel, read by attn_kernel)
__device__ __align__(16) __half g_qh[BB*SS*DD];   // [b][s][d], pre-scaled 1/16
__device__ __align__(16) __half g_ql[BB*SS*DD];
__device__ __align__(16) __half g_kh[BB*SS*DD];   // [b][s][d]
__device__ __align__(16) __half g_kl[BB*SS*DD];
__device__ __align__(16) __half g_vth[BB*SS*DD];  // [b][d][s]  (transposed!)
__device__ __align__(16) __half g_vtl[BB*SS*DD];

__device__ __forceinline__ void split1(float x, __half& h, __half& l) {
    h = __float2half_rn(x);
    l = __float2half_rn(x - __half2float(h));
}
__device__ __forceinline__ unsigned packh(__half a, __half b) {
    __half2 t = __halves2half2(a, b);
    return *reinterpret_cast<unsigned*>(&t);
}

// ---------------------------------------------------------------------------
// Kernel 1: QKV projection (fp32 SIMT), epilogue emits fp16 hi/lo splits.
// q pre-scaled by 1/sqrt(D)=2^-4 (exact); v stored transposed [b][d][s].
// ---------------------------------------------------------------------------
__global__ __launch_bounds__(256) void qkv_kernel(
    const float* __restrict__ x,
    const float* __restrict__ Wq, const float* __restrict__ bq,
    const float* __restrict__ Wk, const float* __restrict__ bk,
    const float* __restrict__ Wv, const float* __restrict__ bv)
{
    const float* W;
    const float* bias;
    if (blockIdx.z == 0)      { W = Wq; bias = bq; }
    else if (blockIdx.z == 1) { W = Wk; bias = bk; }
    else                      { W = Wv; bias = bv; }

    __shared__ float Xs[64][68];
    __shared__ float Ws[64][68];

    const int tid = threadIdx.x;
    const int ty  = tid >> 4;
    const int tx  = tid & 15;
    const int m0  = blockIdx.x * 64;
    const int n0  = blockIdx.y * 64;

    float acc[4][4] = {};

    for (int kc = 0; kc < DD; kc += 64) {
        __syncthreads();
        #pragma unroll
        for (int t = 0; t < 4; t++) {
            int idx = tid + t * 256;
            int row = idx >> 4, c4 = idx & 15;
            *(float4*)&Xs[row][c4*4] = *(const float4*)&x[(m0+row)*DD + kc + c4*4];
            *(float4*)&Ws[row][c4*4] = *(const float4*)&W[(n0+row)*DD + kc + c4*4];
        }
        __syncthreads();

        #pragma unroll 4
        for (int kk = 0; kk < 64; kk += 4) {
            float4 xv[4], wv[4];
            #pragma unroll
            for (int i = 0; i < 4; i++) xv[i] = *(const float4*)&Xs[ty*4+i][kk];
            #pragma unroll
            for (int c = 0; c < 4; c++) wv[c] = *(const float4*)&Ws[tx*4+c][kk];
            #pragma unroll
            for (int i = 0; i < 4; i++)
                #pragma unroll
                for (int c = 0; c < 4; c++)
                    acc[i][c] += xv[i].x*wv[c].x + xv[i].y*wv[c].y
                               + xv[i].z*wv[c].z + xv[i].w*wv[c].w;
        }
    }

    float bc[4];
    #pragma unroll
    for (int c = 0; c < 4; c++) bc[c] = __ldg(&bias[n0 + tx*4 + c]);

    float res[4][4];
    const float qs = (blockIdx.z == 0) ? 0.0625f : 1.0f;
    #pragma unroll
    for (int i = 0; i < 4; i++)
        #pragma unroll
        for (int c = 0; c < 4; c++)
            res[i][c] = (acc[i][c] + bc[c]) * qs;

    if (blockIdx.z != 2) {
        __half* gh = (blockIdx.z == 0) ? g_qh : g_kh;
        __half* gl = (blockIdx.z == 0) ? g_ql : g_kl;
        #pragma unroll
        for (int i = 0; i < 4; i++) {
            __half h[4], l[4];
            #pragma unroll
            for (int c = 0; c < 4; c++) split1(res[i][c], h[c], l[c]);
            size_t off = (size_t)(m0 + ty*4 + i)*DD + n0 + tx*4;
            uint2 uh; uh.x = packh(h[0], h[1]); uh.y = packh(h[2], h[3]);
            uint2 ul; ul.x = packh(l[0], l[1]); ul.y = packh(l[2], l[3]);
            *(uint2*)&gh[off] = uh;
            *(uint2*)&gl[off] = ul;
        }
    } else {
        const int bb = m0 >> 12;              // m0 / SS
        const int s0 = (m0 & (SS-1)) + ty*4;
        #pragma unroll
        for (int c = 0; c < 4; c++) {
            __half h[4], l[4];
            #pragma unroll
            for (int i = 0; i < 4; i++) split1(res[i][c], h[i], l[i]);
            size_t off = ((size_t)bb*DD + n0 + tx*4 + c)*SS + s0;
            uint2 uh; uh.x = packh(h[0], h[1]); uh.y = packh(h[2], h[3]);
            uint2 ul; ul.x = packh(l[0], l[1]); ul.y = packh(l[2], l[3]);
            *(uint2*)&g_vth[off] = uh;
            *(uint2*)&g_vtl[off] = ul;
        }
    }
}

// ---------------------------------------------------------------------------
// Kernel 2: flash attention, fp16 split 3-MMA, ldmatrix + cp.async.
// 256 threads = 8 warps (4 row x 2 col). BQ=BK=64, D=256.
// ---------------------------------------------------------------------------
#define QSTR 264   // halves per Q/K row  (stride % 32 words == 4 -> conflict-free)
#define VSTR 72    // halves per Vt row
#define PSTR 72    // halves per P row
#define ATTN_SMEM_BYTES 228352

__device__ __forceinline__ void ldsm4(unsigned* r, unsigned addr) {
    asm volatile("ldmatrix.sync.aligned.m8n8.x4.shared.b16 {%0,%1,%2,%3}, [%4];\n"
        : "=r"(r[0]), "=r"(r[1]), "=r"(r[2]), "=r"(r[3]) : "r"(addr));
}
__device__ __forceinline__ void mmaf16(float* d, const unsigned* a,
                                       unsigned b0, unsigned b1) {
    asm volatile("mma.sync.aligned.m16n8k16.row.col.f32.f16.f16.f32 "
        "{%0,%1,%2,%3}, {%4,%5,%6,%7}, {%8,%9}, {%0,%1,%2,%3};\n"
        : "+f"(d[0]), "+f"(d[1]), "+f"(d[2]), "+f"(d[3])
        : "r"(a[0]), "r"(a[1]), "r"(a[2]), "r"(a[3]), "r"(b0), "r"(b1));
}
#define CP16(dst, src) \
    asm volatile("cp.async.cg.shared.global [%0], [%1], 16;\n" :: "r"(dst), "l"(src))

__global__ __launch_bounds__(256, 1) void attn_kernel(float* __restrict__ out)
{
    extern __shared__ __half sm[];
    __half* Qh  = sm;
    __half* Ql  = Qh  + 64*QSTR;
    __half* Kh  = Ql  + 64*QSTR;
    __half* Kl  = Kh  + 64*QSTR;
    __half* Vth = Kl  + 64*QSTR;
    __half* Vtl = Vth + 256*VSTR;
    __half* Ph  = Vtl + 256*VSTR;
    __half* Pl  = Ph  + 64*PSTR;
    float* redm = (float*)(Pl + 64*PSTR);   // [2][64]
    float* reds = redm + 128;               // [2][64]

    const int tid  = threadIdx.x;
    const int lane = tid & 31;
    const int w    = tid >> 5;
    const int g    = lane >> 2;
    const int c    = lane & 3;
    const int wr   = w >> 1;
    const int wc   = w & 1;
    const int b    = blockIdx.y;
    const int q0   = blockIdx.x * BQ;
    const int r0   = wr*16 + g;
    const int r1   = r0 + 8;

    const unsigned uQh = (unsigned)__cvta_generic_to_shared(Qh);
    const unsigned uQl = (unsigned)__cvta_generic_to_shared(Ql);
    const unsigned uKh = (unsigned)__cvta_generic_to_shared(Kh);
    const unsigned uKl = (unsigned)__cvta_generic_to_shared(Kl);
    const unsigned uVh = (unsigned)__cvta_generic_to_shared(Vth);
    const unsigned uVl = (unsigned)__cvta_generic_to_shared(Vtl);
    const unsigned uPh = (unsigned)__cvta_generic_to_shared(Ph);
    const unsigned uPl = (unsigned)__cvta_generic_to_shared(Pl);

    // ---- prologue: Q tile cp.async (joins the first commit group) ----
    {
        const __half* qhg = g_qh + ((size_t)b*SS + q0)*DD;
        const __half* qlg = g_ql + ((size_t)b*SS + q0)*DD;
        #pragma unroll
        for (int t = 0; t < 8; t++) {
            int idx = tid + t*256;
            int row = idx >> 5, ck = idx & 31;
            unsigned doff = (unsigned)(row*QSTR + ck*8) * 2u;
            CP16(uQh + doff, qhg + row*DD + ck*8);
            CP16(uQl + doff, qlg + row*DD + ck*8);
        }
    }

    // ---- ldmatrix per-lane address bases (byte offsets into smem) ----
    const int lrow = lane & 7;
    const int p8r  = (lane >> 3) & 1;   // +8 rows  (matrices 1,3)
    const int p8c  = (lane >> 4) & 1;   // +8 cols  (matrices 2,3)
    const unsigned aQ  = ((wr*16  + lrow + p8r*8)*QSTR + p8c*8) * 2u;
    const unsigned bK  = ((wc*32  + lrow + p8r*8)*QSTR + p8c*8) * 2u;
    const unsigned aP  = ((wr*16  + lrow + p8r*8)*PSTR + p8c*8) * 2u;
    const unsigned bV  = ((wc*128 + lrow + p8r*8)*VSTR + p8c*8) * 2u;

    float m0 = -INFINITY, m1 = -INFINITY, lsum0 = 0.f, lsum1 = 0.f;
    float O[16][4];
    #pragma unroll
    for (int nf = 0; nf < 16; nf++)
        #pragma unroll
        for (int r = 0; r < 4; r++) O[nf][r] = 0.f;

    const __half* khg0 = g_kh + (size_t)b*SS*DD;
    const __half* klg0 = g_kl + (size_t)b*SS*DD;
    const __half* vhg0 = g_vth + (size_t)b*DD*SS;
    const __half* vlg0 = g_vtl + (size_t)b*DD*SS;

    for (int jt = 0; jt < SS; jt += BK) {
        __syncthreads();   // all reads of Kh/Vt/P from previous iter done

        // ---- K/V tile loads: pure cp.async, no conversion ----
        const __half* khg = khg0 + (size_t)jt*DD;
        const __half* klg = klg0 + (size_t)jt*DD;
        #pragma unroll
        for (int t = 0; t < 8; t++) {
            int idx = tid + t*256;
            int row = idx >> 5, ck = idx & 31;
            unsigned doff = (unsigned)(row*QSTR + ck*8) * 2u;
            CP16(uKh + doff, khg + row*DD + ck*8);
            CP16(uKl + doff, klg + row*DD + ck*8);
            int vd = idx >> 3, vk = idx & 7;
            unsigned voff = (unsigned)(vd*VSTR + vk*8) * 2u;
            CP16(uVh + voff, vhg0 + (size_t)vd*SS + jt + vk*8);
            CP16(uVl + voff, vlg0 + (size_t)vd*SS + jt + vk*8);
        }
        asm volatile("cp.async.commit_group;\n");
        asm volatile("cp.async.wait_group 0;\n");
        __syncthreads();

        // ---- S = Q K^T (warp 16x32), fp16 split 3-MMA ----
        float S[4][4];
        #pragma unroll
        for (int nf = 0; nf < 4; nf++)
            #pragma unroll
            for (int r = 0; r < 4; r++) S[nf][r] = 0.f;

        #pragma unroll
        for (int ks = 0; ks < 16; ks++) {
            unsigned ah[4], al[4];
            ldsm4(ah, uQh + aQ + ks*32);
            ldsm4(al, uQl + aQ + ks*32);
            #pragma unroll
            for (int p = 0; p < 2; p++) {
                unsigned bh[4], bl[4];
                const unsigned po = (unsigned)(p * 16*QSTR*2);
                ldsm4(bh, uKh + bK + po + ks*32);
                ldsm4(bl, uKl + bK + po + ks*32);
                mmaf16(S[2*p],   ah, bh[0], bh[2]);
                mmaf16(S[2*p],   al, bh[0], bh[2]);
                mmaf16(S[2*p],   ah, bl[0], bl[2]);
                mmaf16(S[2*p+1], ah, bh[1], bh[3]);
                mmaf16(S[2*p+1], al, bh[1], bh[3]);
                mmaf16(S[2*p+1], ah, bl[1], bl[3]);
            }
        }

        // ---- online softmax ----
        float rm0 = -INFINITY, rm1 = -INFINITY;
        #pragma unroll
        for (int nf = 0; nf < 4; nf++) {
            rm0 = fmaxf(rm0, fmaxf(S[nf][0], S[nf][1]));
            rm1 = fmaxf(rm1, fmaxf(S[nf][2], S[nf][3]));
        }
        rm0 = fmaxf(rm0, __shfl_xor_sync(0xffffffffu, rm0, 1));
        rm0 = fmaxf(rm0, __shfl_xor_sync(0xffffffffu, rm0, 2));
        rm1 = fmaxf(rm1, __shfl_xor_sync(0xffffffffu, rm1, 1));
        rm1 = fmaxf(rm1, __shfl_xor_sync(0xffffffffu, rm1, 2));
        if (c == 0) {
            redm[wc*64 + r0] = rm0;
            redm[wc*64 + r1] = rm1;
        }
        __syncthreads();

        float mn0 = fmaxf(m0, fmaxf(redm[r0], redm[64 + r0]));
        float mn1 = fmaxf(m1, fmaxf(redm[r1], redm[64 + r1]));

        float ps0 = 0.f, ps1 = 0.f;
        #pragma unroll
        for (int nf = 0; nf < 4; nf++) {
            float p0 = __expf(S[nf][0] - mn0);
            float p1 = __expf(S[nf][1] - mn0);
            float p2 = __expf(S[nf][2] - mn1);
            float p3 = __expf(S[nf][3] - mn1);
            ps0 += p0 + p1;
            ps1 += p2 + p3;
            const int col = wc*32 + nf*8 + 2*c;
            __half h0, l0, h1, l1;
            split1(p0, h0, l0); split1(p1, h1, l1);
            *(unsigned*)&Ph[r0*PSTR + col] = packh(h0, h1);
            *(unsigned*)&Pl[r0*PSTR + col] = packh(l0, l1);
            split1(p2, h0, l0); split1(p3, h1, l1);
            *(unsigned*)&Ph[r1*PSTR + col] = packh(h0, h1);
            *(unsigned*)&Pl[r1*PSTR + col] = packh(l0, l1);
        }
        ps0 += __shfl_xor_sync(0xffffffffu, ps0, 1);
        ps0 += __shfl_xor_sync(0xffffffffu, ps0, 2);
        ps1 += __shfl_xor_sync(0xffffffffu, ps1, 1);
        ps1 += __shfl_xor_sync(0xffffffffu, ps1, 2);
        if (c == 0) {
            reds[wc*64 + r0] = ps0;
            reds[wc*64 + r1] = ps1;
        }
        __syncthreads();   // reds + P tiles visible

        float a0f = __expf(m0 - mn0);
        float a1f = __expf(m1 - mn1);
        lsum0 = lsum0*a0f + reds[r0] + reds[64 + r0];
        lsum1 = lsum1*a1f + reds[r1] + reds[64 + r1];
        m0 = mn0; m1 = mn1;
        #pragma unroll
        for (int nf = 0; nf < 16; nf++) {
            O[nf][0] *= a0f; O[nf][1] *= a0f;
            O[nf][2] *= a1f; O[nf][3] *= a1f;
        }

        // ---- O += P V (warp 16x128), fp16 split 3-MMA ----
        #pragma unroll
        for (int kk = 0; kk < 4; kk++) {
            unsigned ah[4], al[4];
            ldsm4(ah, uPh + aP + kk*32);
            ldsm4(al, uPl + aP + kk*32);
            #pragma unroll
            for (int p = 0; p < 8; p++) {
                unsigned bh[4], bl[4];
                const unsigned po = (unsigned)(p * 16*VSTR*2);
                ldsm4(bh, uVh + bV + po + kk*32);
                ldsm4(bl, uVl + bV + po + kk*32);
                mmaf16(O[2*p],   ah, bh[0], bh[2]);
                mmaf16(O[2*p],   al, bh[0], bh[2]);
                mmaf16(O[2*p],   ah, bl[0], bl[2]);
                mmaf16(O[2*p+1], ah, bh[1], bh[3]);
                mmaf16(O[2*p+1], al, bh[1], bh[3]);
                mmaf16(O[2*p+1], ah, bl[1], bl[3]);
            }
        }
    }

    // ---- normalize + store ----
    const float inv0 = 1.0f / lsum0;
    const float inv1 = 1.0f / lsum1;
    #pragma unroll
    for (int nf = 0; nf < 16; nf++) {
        const int col = wc*128 + nf*8 + 2*c;
        float2 o0, o1;
        o0.x = O[nf][0]*inv0; o0.y = O[nf][1]*inv0;
        o1.x = O[nf][2]*inv1; o1.y = O[nf][3]*inv1;
        *(float2*)&out[((size_t)b*SS + q0 + r0)*DD + col] = o0;
        *(float2*)&out[((size_t)b*SS + q0 + r1)*DD + col] = o1;
    }
}

// ---------------------------------------------------------------------------
// Launch
// ---------------------------------------------------------------------------
extern "C" void kernel_launch(void* const* d_in, const int* in_sizes, int n_in,
                              void* d_out, int out_size)
{
    (void)in_sizes; (void)n_in; (void)out_size;
    const float* x  = (const float*)d_in[0];
    const float* Wq = (const float*)d_in[1];
    const float* bq = (const float*)d_in[2];
    const float* Wk = (const float*)d_in[3];
    const float* bk = (const float*)d_in[4];
    const float* Wv = (const float*)d_in[5];
    const float* bv = (const float*)d_in[6];
    float* out = (float*)d_out;

    dim3 grid_qkv((BB*SS)/64, DD/64, 3);
    qkv_kernel<<<grid_qkv, 256>>>(x, Wq, bq, Wk, bk, Wv, bv);

    cudaFuncSetAttribute(attn_kernel, cudaFuncAttributeMaxDynamicSharedMemorySize,
                         ATTN_SMEM_BYTES);
    dim3 grid_attn(SS/BQ, BB);
    attn_kernel<<<grid_attn, 256, ATTN_SMEM_BYTES>>>(out);
}

// round 7
// speedup vs baseline: 4.6143x; 1.4709x over previous
#include <cuda_runtime.h>
#include <cuda_fp16.h>
#include <math.h>

#define BB 4
#define SS 4096
#define DD 256
#define BQ 64
#define BK 64

// fp16 hi/lo split tensors (device globals: allocation-free rule)
__device__ __align__(16) __half g_xh[BB*SS*DD];   // [b][s][d]  split of input x
__device__ __align__(16) __half g_xl[BB*SS*DD];
__device__ __align__(16) __half g_qh[BB*SS*DD];   // [b][s][d], pre-scaled 1/16
__device__ __align__(16) __half g_ql[BB*SS*DD];
__device__ __align__(16) __half g_kh[BB*SS*DD];   // [b][s][d]
__device__ __align__(16) __half g_kl[BB*SS*DD];
__device__ __align__(16) __half g_vth[BB*SS*DD];  // [b][d][s]  (transposed)
__device__ __align__(16) __half g_vtl[BB*SS*DD];

__device__ __forceinline__ void split1(float x, __half& h, __half& l) {
    h = __float2half_rn(x);
    l = __float2half_rn(x - __half2float(h));
}
__device__ __forceinline__ unsigned packh(__half a, __half b) {
    __half2 t = __halves2half2(a, b);
    return *reinterpret_cast<unsigned*>(&t);
}
__device__ __forceinline__ void ldsm4(unsigned* r, unsigned addr) {
    asm volatile("ldmatrix.sync.aligned.m8n8.x4.shared.b16 {%0,%1,%2,%3}, [%4];\n"
        : "=r"(r[0]), "=r"(r[1]), "=r"(r[2]), "=r"(r[3]) : "r"(addr));
}
__device__ __forceinline__ void mmaf16(float* d, const unsigned* a,
                                       unsigned b0, unsigned b1) {
    asm volatile("mma.sync.aligned.m16n8k16.row.col.f32.f16.f16.f32 "
        "{%0,%1,%2,%3}, {%4,%5,%6,%7}, {%8,%9}, {%0,%1,%2,%3};\n"
        : "+f"(d[0]), "+f"(d[1]), "+f"(d[2]), "+f"(d[3])
        : "r"(a[0]), "r"(a[1]), "r"(a[2]), "r"(a[3]), "r"(b0), "r"(b1));
}
#define CP16(dst, src) \
    asm volatile("cp.async.cg.shared.global [%0], [%1], 16;\n" :: "r"(dst), "l"(src))
#define CP_COMMIT() asm volatile("cp.async.commit_group;\n")
#define CP_WAIT0()  asm volatile("cp.async.wait_group 0;\n")
#define CP_WAIT1()  asm volatile("cp.async.wait_group 1;\n")

// ---------------------------------------------------------------------------
// Kernel 0: split input x into fp16 hi/lo.
// ---------------------------------------------------------------------------
__global__ __launch_bounds__(256) void split_x_kernel(const float* __restrict__ x)
{
    int idx = blockIdx.x * 256 + threadIdx.x;          // one float4 each
    float4 f = ((const float4*)x)[idx];
    __half h0,l0,h1,l1,h2,l2,h3,l3;
    split1(f.x,h0,l0); split1(f.y,h1,l1); split1(f.z,h2,l2); split1(f.w,h3,l3);
    uint2 uh; uh.x = packh(h0,h1); uh.y = packh(h2,h3);
    uint2 ul; ul.x = packh(l0,l1); ul.y = packh(l2,l3);
    *(uint2*)&g_xh[(size_t)idx*4] = uh;
    *(uint2*)&g_xl[(size_t)idx*4] = ul;
}

// ---------------------------------------------------------------------------
// Kernel 1: QKV projection on tensor cores (split-fp16 3-MMA).
// Block computes 128(m) x 64(n), whole K=256 staged in smem.
// 8 warps = 4(row) x 2(col); warp tile 32x32: 2 m-frags x 4 n-frags x 16 ks.
// z==2 (V) output transposed through smem, then coalesced [b][d][s] stores.
// ---------------------------------------------------------------------------
#define GSTR 264   // halves per smem row (k-stride); stride%32 words == 4
#define QKV_SMEM_BYTES ((2*128*GSTR + 2*64*GSTR) * 2)   // 202,752

__global__ __launch_bounds__(256, 1) void qkv_mma_kernel(
    const float* __restrict__ Wq, const float* __restrict__ bq,
    const float* __restrict__ Wk, const float* __restrict__ bk,
    const float* __restrict__ Wv, const float* __restrict__ bv)
{
    const float* W;
    const float* bias;
    if (blockIdx.z == 0)      { W = Wq; bias = bq; }
    else if (blockIdx.z == 1) { W = Wk; bias = bk; }
    else                      { W = Wv; bias = bv; }

    extern __shared__ __half qsm[];
    __half* Xh = qsm;
    __half* Xl = Xh + 128*GSTR;
    __half* Wh = Xl + 128*GSTR;
    __half* Wl = Wh + 64*GSTR;

    const int tid  = threadIdx.x;
    const int lane = tid & 31;
    const int w    = tid >> 5;
    const int g    = lane >> 2;
    const int c    = lane & 3;
    const int wr   = w >> 1;        // 0..3
    const int wc   = w & 1;         // 0..1
    const int m0   = blockIdx.x * 128;
    const int n0   = blockIdx.y * 64;

    const unsigned uXh = (unsigned)__cvta_generic_to_shared(Xh);
    const unsigned uXl = (unsigned)__cvta_generic_to_shared(Xl);
    const unsigned uWh = (unsigned)__cvta_generic_to_shared(Wh);
    const unsigned uWl = (unsigned)__cvta_generic_to_shared(Wl);

    // ---- X tiles via cp.async (already fp16 split) ----
    {
        const __half* xh = g_xh + (size_t)m0*DD;
        const __half* xl = g_xl + (size_t)m0*DD;
        #pragma unroll
        for (int t = 0; t < 16; t++) {
            int idx = tid + t*256;
            int row = idx >> 5, ck = idx & 31;
            unsigned doff = (unsigned)(row*GSTR + ck*8) * 2u;
            CP16(uXh + doff, xh + (size_t)row*DD + ck*8);
            CP16(uXl + doff, xl + (size_t)row*DD + ck*8);
        }
        CP_COMMIT();
    }
    // ---- W tile: fp32 loads, split into smem ----
    #pragma unroll
    for (int i = 0; i < 16; i++) {
        int idx = tid + i*256;
        int row = idx >> 6, c4 = idx & 63;
        float4 f = __ldg((const float4*)&W[(size_t)(n0+row)*DD + c4*4]);
        __half h0,l0,h1,l1,h2,l2,h3,l3;
        split1(f.x,h0,l0); split1(f.y,h1,l1); split1(f.z,h2,l2); split1(f.w,h3,l3);
        unsigned* ph = (unsigned*)&Wh[row*GSTR + c4*4];
        unsigned* pl = (unsigned*)&Wl[row*GSTR + c4*4];
        ph[0] = packh(h0,h1); ph[1] = packh(h2,h3);
        pl[0] = packh(l0,l1); pl[1] = packh(l2,l3);
    }
    CP_WAIT0();
    __syncthreads();

    // ---- fragment address bases ----
    const int lrow = lane & 7;
    const int p8r  = (lane >> 3) & 1;
    const int p8c  = (lane >> 4) & 1;
    const unsigned aX0 = ((wr*32      + lrow + p8r*8)*GSTR + p8c*8) * 2u;
    const unsigned aX1 = ((wr*32 + 16 + lrow + p8r*8)*GSTR + p8c*8) * 2u;
    const unsigned bW  = ((wc*32      + lrow + p8r*8)*GSTR + p8c*8) * 2u;

    float acc[2][4][4];
    #pragma unroll
    for (int mf = 0; mf < 2; mf++)
        #pragma unroll
        for (int nf = 0; nf < 4; nf++)
            #pragma unroll
            for (int r = 0; r < 4; r++) acc[mf][nf][r] = 0.f;

    #pragma unroll
    for (int ks = 0; ks < 16; ks++) {
        unsigned ah[2][4], al[2][4];
        ldsm4(ah[0], uXh + aX0 + ks*32);
        ldsm4(al[0], uXl + aX0 + ks*32);
        ldsm4(ah[1], uXh + aX1 + ks*32);
        ldsm4(al[1], uXl + aX1 + ks*32);
        #pragma unroll
        for (int p = 0; p < 2; p++) {
            unsigned bh[4], bl[4];
            const unsigned po = (unsigned)(p * 16*GSTR*2);
            ldsm4(bh, uWh + bW + po + ks*32);
            ldsm4(bl, uWl + bW + po + ks*32);
            #pragma unroll
            for (int mf = 0; mf < 2; mf++) {
                mmaf16(acc[mf][2*p],   ah[mf], bh[0], bh[2]);
                mmaf16(acc[mf][2*p],   al[mf], bh[0], bh[2]);
                mmaf16(acc[mf][2*p],   ah[mf], bl[0], bl[2]);
                mmaf16(acc[mf][2*p+1], ah[mf], bh[1], bh[3]);
                mmaf16(acc[mf][2*p+1], al[mf], bh[1], bh[3]);
                mmaf16(acc[mf][2*p+1], ah[mf], bl[1], bl[3]);
            }
        }
    }

    // ---- epilogue ----
    float bb2[4][2];
    #pragma unroll
    for (int nf = 0; nf < 4; nf++) {
        int col = n0 + wc*32 + nf*8 + 2*c;
        bb2[nf][0] = __ldg(&bias[col]);
        bb2[nf][1] = __ldg(&bias[col+1]);
    }
    const float qs = (blockIdx.z == 0) ? 0.0625f : 1.0f;

    if (blockIdx.z != 2) {
        __half* gh = (blockIdx.z == 0) ? g_qh : g_kh;
        __half* gl = (blockIdx.z == 0) ? g_ql : g_kl;
        #pragma unroll
        for (int mf = 0; mf < 2; mf++) {
            int r0g = m0 + wr*32 + mf*16 + g;
            #pragma unroll
            for (int nf = 0; nf < 4; nf++) {
                int col = n0 + wc*32 + nf*8 + 2*c;
                float v0 = (acc[mf][nf][0] + bb2[nf][0]) * qs;
                float v1 = (acc[mf][nf][1] + bb2[nf][1]) * qs;
                float v2 = (acc[mf][nf][2] + bb2[nf][0]) * qs;
                float v3 = (acc[mf][nf][3] + bb2[nf][1]) * qs;
                __half h0,l0,h1,l1;
                split1(v0,h0,l0); split1(v1,h1,l1);
                *(unsigned*)&gh[(size_t)r0g*DD + col] = packh(h0,h1);
                *(unsigned*)&gl[(size_t)r0g*DD + col] = packh(l0,l1);
                split1(v2,h0,l0); split1(v3,h1,l1);
                *(unsigned*)&gh[(size_t)(r0g+8)*DD + col] = packh(h0,h1);
                *(unsigned*)&gl[(size_t)(r0g+8)*DD + col] = packh(l0,l1);
            }
        }
    } else {
        // V: transpose through smem (reuse X area), then coalesced stores.
        __syncthreads();           // everyone done reading Xh/Xl
        __half* Th = qsm;          // [64 d][136 s]
        __half* Tl = qsm + 64*136;
        #pragma unroll
        for (int mf = 0; mf < 2; mf++) {
            int s0 = wr*32 + mf*16 + g;
            #pragma unroll
            for (int nf = 0; nf < 4; nf++) {
                int d0 = wc*32 + nf*8 + 2*c;
                float v0 = acc[mf][nf][0] + bb2[nf][0];
                float v1 = acc[mf][nf][1] + bb2[nf][1];
                float v2 = acc[mf][nf][2] + bb2[nf][0];
                float v3 = acc[mf][nf][3] + bb2[nf][1];
                __half h, l;
                split1(v0,h,l); Th[d0*136 + s0] = h;      Tl[d0*136 + s0] = l;
                split1(v1,h,l); Th[(d0+1)*136 + s0] = h;  Tl[(d0+1)*136 + s0] = l;
                split1(v2,h,l); Th[d0*136 + s0+8] = h;    Tl[d0*136 + s0+8] = l;
                split1(v3,h,l); Th[(d0+1)*136 + s0+8] = h;Tl[(d0+1)*136 + s0+8] = l;
            }
        }
        __syncthreads();
        const int bbat = m0 >> 12;
        const int sbase = m0 & (SS-1);
        #pragma unroll
        for (int t = 0; t < 4; t++) {
            int idx = tid + t*256;
            int d = idx >> 4, ch = idx & 15;
            uint4 vh = *(uint4*)&Th[d*136 + ch*8];
            uint4 vl = *(uint4*)&Tl[d*136 + ch*8];
            size_t off = ((size_t)(bbat*DD + n0 + d))*SS + sbase + ch*8;
            *(uint4*)&g_vth[off] = vh;
            *(uint4*)&g_vtl[off] = vl;
        }
    }
}

// ---------------------------------------------------------------------------
// Kernel 2: flash attention, fp16 split 3-MMA, ldmatrix + PIPELINED cp.async.
// V(j) prefetched during S(j); K(j+1) prefetched during softmax-tail + PV(j).
// ---------------------------------------------------------------------------
#define QSTR 264
#define VSTR 72
#define PSTR 72
#define ATTN_SMEM_BYTES 228352

__global__ __launch_bounds__(256, 1) void attn_kernel(float* __restrict__ out)
{
    extern __shared__ __half sm[];
    __half* Qh  = sm;
    __half* Ql  = Qh  + 64*QSTR;
    __half* Kh  = Ql  + 64*QSTR;
    __half* Kl  = Kh  + 64*QSTR;
    __half* Vth = Kl  + 64*QSTR;
    __half* Vtl = Vth + 256*VSTR;
    __half* Ph  = Vtl + 256*VSTR;
    __half* Pl  = Ph  + 64*PSTR;
    float* redm = (float*)(Pl + 64*PSTR);   // [2][64]
    float* reds = redm + 128;               // [2][64]

    const int tid  = threadIdx.x;
    const int lane = tid & 31;
    const int w    = tid >> 5;
    const int g    = lane >> 2;
    const int c    = lane & 3;
    const int wr   = w >> 1;
    const int wc   = w & 1;
    const int b    = blockIdx.y;
    const int q0   = blockIdx.x * BQ;
    const int r0   = wr*16 + g;
    const int r1   = r0 + 8;

    const unsigned uQh = (unsigned)__cvta_generic_to_shared(Qh);
    const unsigned uQl = (unsigned)__cvta_generic_to_shared(Ql);
    const unsigned uKh = (unsigned)__cvta_generic_to_shared(Kh);
    const unsigned uKl = (unsigned)__cvta_generic_to_shared(Kl);
    const unsigned uVh = (unsigned)__cvta_generic_to_shared(Vth);
    const unsigned uVl = (unsigned)__cvta_generic_to_shared(Vtl);
    const unsigned uPh = (unsigned)__cvta_generic_to_shared(Ph);
    const unsigned uPl = (unsigned)__cvta_generic_to_shared(Pl);

    const __half* khg0 = g_kh + (size_t)b*SS*DD;
    const __half* klg0 = g_kl + (size_t)b*SS*DD;
    const __half* vhg0 = g_vth + (size_t)b*DD*SS;
    const __half* vlg0 = g_vtl + (size_t)b*DD*SS;

    // ---- prologue: Q + K(0) in one cp.async group ----
    {
        const __half* qhg = g_qh + ((size_t)b*SS + q0)*DD;
        const __half* qlg = g_ql + ((size_t)b*SS + q0)*DD;
        #pragma unroll
        for (int t = 0; t < 8; t++) {
            int idx = tid + t*256;
            int row = idx >> 5, ck = idx & 31;
            unsigned doff = (unsigned)(row*QSTR + ck*8) * 2u;
            CP16(uQh + doff, qhg + row*DD + ck*8);
            CP16(uQl + doff, qlg + row*DD + ck*8);
            CP16(uKh + doff, khg0 + (size_t)row*DD + ck*8);
            CP16(uKl + doff, klg0 + (size_t)row*DD + ck*8);
        }
        CP_COMMIT();
    }

    const int lrow = lane & 7;
    const int p8r  = (lane >> 3) & 1;
    const int p8c  = (lane >> 4) & 1;
    const unsigned aQ = ((wr*16  + lrow + p8r*8)*QSTR + p8c*8) * 2u;
    const unsigned bK = ((wc*32  + lrow + p8r*8)*QSTR + p8c*8) * 2u;
    const unsigned aP = ((wr*16  + lrow + p8r*8)*PSTR + p8c*8) * 2u;
    const unsigned bV = ((wc*128 + lrow + p8r*8)*VSTR + p8c*8) * 2u;

    float m0 = -INFINITY, m1 = -INFINITY, lsum0 = 0.f, lsum1 = 0.f;
    float O[16][4];
    #pragma unroll
    for (int nf = 0; nf < 16; nf++)
        #pragma unroll
        for (int r = 0; r < 4; r++) O[nf][r] = 0.f;

    for (int jt = 0; jt < SS; jt += BK) {
        __syncthreads();   // V buffer + P free (PV(j-1) complete)

        // ---- prefetch V(j) (consumed after softmax) ----
        #pragma unroll
        for (int t = 0; t < 8; t++) {
            int idx = tid + t*256;
            int vd = idx >> 3, vk = idx & 7;
            unsigned voff = (unsigned)(vd*VSTR + vk*8) * 2u;
            CP16(uVh + voff, vhg0 + (size_t)vd*SS + jt + vk*8);
            CP16(uVl + voff, vlg0 + (size_t)vd*SS + jt + vk*8);
        }
        CP_COMMIT();       // pending: {K(j) [or prologue], V(j)}
        CP_WAIT1();        // K(j) (older group) complete
        __syncthreads();   // K visible to all warps

        // ---- S = Q K^T (warp 16x32), fp16 split 3-MMA ----
        float S[4][4];
        #pragma unroll
        for (int nf = 0; nf < 4; nf++)
            #pragma unroll
            for (int r = 0; r < 4; r++) S[nf][r] = 0.f;

        #pragma unroll
        for (int ks = 0; ks < 16; ks++) {
            unsigned ah[4], al[4];
            ldsm4(ah, uQh + aQ + ks*32);
            ldsm4(al, uQl + aQ + ks*32);
            #pragma unroll
            for (int p = 0; p < 2; p++) {
                unsigned bh[4], bl[4];
                const unsigned po = (unsigned)(p * 16*QSTR*2);
                ldsm4(bh, uKh + bK + po + ks*32);
                ldsm4(bl, uKl + bK + po + ks*32);
                mmaf16(S[2*p],   ah, bh[0], bh[2]);
                mmaf16(S[2*p],   al, bh[0], bh[2]);
                mmaf16(S[2*p],   ah, bl[0], bl[2]);
                mmaf16(S[2*p+1], ah, bh[1], bh[3]);
                mmaf16(S[2*p+1], al, bh[1], bh[3]);
                mmaf16(S[2*p+1], ah, bl[1], bl[3]);
            }
        }

        // ---- online softmax ----
        float rm0 = -INFINITY, rm1 = -INFINITY;
        #pragma unroll
        for (int nf = 0; nf < 4; nf++) {
            rm0 = fmaxf(rm0, fmaxf(S[nf][0], S[nf][1]));
            rm1 = fmaxf(rm1, fmaxf(S[nf][2], S[nf][3]));
        }
        rm0 = fmaxf(rm0, __shfl_xor_sync(0xffffffffu, rm0, 1));
        rm0 = fmaxf(rm0, __shfl_xor_sync(0xffffffffu, rm0, 2));
        rm1 = fmaxf(rm1, __shfl_xor_sync(0xffffffffu, rm1, 1));
        rm1 = fmaxf(rm1, __shfl_xor_sync(0xffffffffu, rm1, 2));
        if (c == 0) {
            redm[wc*64 + r0] = rm0;
            redm[wc*64 + r1] = rm1;
        }
        __syncthreads();   // also: all warps finished reading K tile

        // ---- prefetch K(j+1) now that K buffer is free ----
        if (jt + BK < SS) {
            const __half* khg = khg0 + (size_t)(jt+BK)*DD;
            const __half* klg = klg0 + (size_t)(jt+BK)*DD;
            #pragma unroll
            for (int t = 0; t < 8; t++) {
                int idx = tid + t*256;
                int row = idx >> 5, ck = idx & 31;
                unsigned doff = (unsigned)(row*QSTR + ck*8) * 2u;
                CP16(uKh + doff, khg + row*DD + ck*8);
                CP16(uKl + doff, klg + row*DD + ck*8);
            }
            CP_COMMIT();   // pending: {V(j), K(j+1)}
        }

        float mn0 = fmaxf(m0, fmaxf(redm[r0], redm[64 + r0]));
        float mn1 = fmaxf(m1, fmaxf(redm[r1], redm[64 + r1]));

        float ps0 = 0.f, ps1 = 0.f;
        #pragma unroll
        for (int nf = 0; nf < 4; nf++) {
            float p0 = __expf(S[nf][0] - mn0);
            float p1 = __expf(S[nf][1] - mn0);
            float p2 = __expf(S[nf][2] - mn1);
            float p3 = __expf(S[nf][3] - mn1);
            ps0 += p0 + p1;
            ps1 += p2 + p3;
            const int col = wc*32 + nf*8 + 2*c;
            __half h0, l0, h1, l1;
            split1(p0, h0, l0); split1(p1, h1, l1);
            *(unsigned*)&Ph[r0*PSTR + col] = packh(h0, h1);
            *(unsigned*)&Pl[r0*PSTR + col] = packh(l0, l1);
            split1(p2, h0, l0); split1(p3, h1, l1);
            *(unsigned*)&Ph[r1*PSTR + col] = packh(h0, h1);
            *(unsigned*)&Pl[r1*PSTR + col] = packh(l0, l1);
        }
        ps0 += __shfl_xor_sync(0xffffffffu, ps0, 1);
        ps0 += __shfl_xor_sync(0xffffffffu, ps0, 2);
        ps1 += __shfl_xor_sync(0xffffffffu, ps1, 1);
        ps1 += __shfl_xor_sync(0xffffffffu, ps1, 2);
        if (c == 0) {
            reds[wc*64 + r0] = ps0;
            reds[wc*64 + r1] = ps1;
        }

        if (jt + BK < SS) { CP_WAIT1(); }   // V(j) done, K(j+1) may fly
        else              { CP_WAIT0(); }   // last iter: drain V(j)
        __syncthreads();   // reds + P + V visible

        float a0f = __expf(m0 - mn0);
        float a1f = __expf(m1 - mn1);
        lsum0 = lsum0*a0f + reds[r0] + reds[64 + r0];
        lsum1 = lsum1*a1f + reds[r1] + reds[64 + r1];
        m0 = mn0; m1 = mn1;
        #pragma unroll
        for (int nf = 0; nf < 16; nf++) {
            O[nf][0] *= a0f; O[nf][1] *= a0f;
            O[nf][2] *= a1f; O[nf][3] *= a1f;
        }

        // ---- O += P V (warp 16x128), fp16 split 3-MMA ----
        #pragma unroll
        for (int kk = 0; kk < 4; kk++) {
            unsigned ah[4], al[4];
            ldsm4(ah, uPh + aP + kk*32);
            ldsm4(al, uPl + aP + kk*32);
            #pragma unroll
            for (int p = 0; p < 8; p++) {
                unsigned bh[4], bl[4];
                const unsigned po = (unsigned)(p * 16*VSTR*2);
                ldsm4(bh, uVh + bV + po + kk*32);
                ldsm4(bl, uVl + bV + po + kk*32);
                mmaf16(O[2*p],   ah, bh[0], bh[2]);
                mmaf16(O[2*p],   al, bh[0], bh[2]);
                mmaf16(O[2*p],   ah, bl[0], bl[2]);
                mmaf16(O[2*p+1], ah, bh[1], bh[3]);
                mmaf16(O[2*p+1], al, bh[1], bh[3]);
                mmaf16(O[2*p+1], ah, bl[1], bl[3]);
            }
        }
    }

    // ---- normalize + store ----
    const float inv0 = 1.0f / lsum0;
    const float inv1 = 1.0f / lsum1;
    #pragma unroll
    for (int nf = 0; nf < 16; nf++) {
        const int col = wc*128 + nf*8 + 2*c;
        float2 o0, o1;
        o0.x = O[nf][0]*inv0; o0.y = O[nf][1]*inv0;
        o1.x = O[nf][2]*inv1; o1.y = O[nf][3]*inv1;
        *(float2*)&out[((size_t)b*SS + q0 + r0)*DD + col] = o0;
        *(float2*)&out[((size_t)b*SS + q0 + r1)*DD + col] = o1;
    }
}

// ---------------------------------------------------------------------------
// Launch
// ---------------------------------------------------------------------------
extern "C" void kernel_launch(void* const* d_in, const int* in_sizes, int n_in,
                              void* d_out, int out_size)
{
    (void)in_sizes; (void)n_in; (void)out_size;
    const float* x  = (const float*)d_in[0];
    const float* Wq = (const float*)d_in[1];
    const float* bq = (const float*)d_in[2];
    const float* Wk = (const float*)d_in[3];
    const float* bk = (const float*)d_in[4];
    const float* Wv = (const float*)d_in[5];
    const float* bv = (const float*)d_in[6];
    float* out = (float*)d_out;

    split_x_kernel<<<(BB*SS*DD)/(4*256), 256>>>(x);

    cudaFuncSetAttribute(qkv_mma_kernel, cudaFuncAttributeMaxDynamicSharedMemorySize,
                         QKV_SMEM_BYTES);
    dim3 grid_qkv((BB*SS)/128, DD/64, 3);
    qkv_mma_kernel<<<grid_qkv, 256, QKV_SMEM_BYTES>>>(Wq, bq, Wk, bk, Wv, bv);

    cudaFuncSetAttribute(attn_kernel, cudaFuncAttributeMaxDynamicSharedMemorySize,
                         ATTN_SMEM_BYTES);
    dim3 grid_attn(SS/BQ, BB);
    attn_kernel<<<grid_attn, 256, ATTN_SMEM_BYTES>>>(out);
}

// round 8
// speedup vs baseline: 6.5182x; 1.4126x over previous
#include <cuda_runtime.h>
#include <cuda_fp16.h>
#include <math.h>

#define BB 4
#define SS 4096
#define DD 256
#define BQ 64
#define BK 64

// fp16 split tensors (device globals: allocation-free rule)
__device__ __align__(16) __half g_xh[BB*SS*DD];   // [b][s][d] split of input x
__device__ __align__(16) __half g_xl[BB*SS*DD];
__device__ __align__(16) __half g_qh[BB*SS*DD];   // [b][s][d], pre-scaled 1/16
__device__ __align__(16) __half g_ql[BB*SS*DD];
__device__ __align__(16) __half g_kh[BB*SS*DD];   // [b][s][d]   (hi only)
__device__ __align__(16) __half g_vth[BB*SS*DD];  // [b][d][s]   (hi only, transposed)

__device__ __forceinline__ void split1(float x, __half& h, __half& l) {
    h = __float2half_rn(x);
    l = __float2half_rn(x - __half2float(h));
}
__device__ __forceinline__ unsigned packh(__half a, __half b) {
    __half2 t = __halves2half2(a, b);
    return *reinterpret_cast<unsigned*>(&t);
}
__device__ __forceinline__ void ldsm4(unsigned* r, unsigned addr) {
    asm volatile("ldmatrix.sync.aligned.m8n8.x4.shared.b16 {%0,%1,%2,%3}, [%4];\n"
        : "=r"(r[0]), "=r"(r[1]), "=r"(r[2]), "=r"(r[3]) : "r"(addr));
}
__device__ __forceinline__ void mmaf16(float* d, const unsigned* a,
                                       unsigned b0, unsigned b1) {
    asm volatile("mma.sync.aligned.m16n8k16.row.col.f32.f16.f16.f32 "
        "{%0,%1,%2,%3}, {%4,%5,%6,%7}, {%8,%9}, {%0,%1,%2,%3};\n"
        : "+f"(d[0]), "+f"(d[1]), "+f"(d[2]), "+f"(d[3])
        : "r"(a[0]), "r"(a[1]), "r"(a[2]), "r"(a[3]), "r"(b0), "r"(b1));
}
#define CP16(dst, src) \
    asm volatile("cp.async.cg.shared.global [%0], [%1], 16;\n" :: "r"(dst), "l"(src))
#define CP_COMMIT() asm volatile("cp.async.commit_group;\n")
#define CP_WAIT0()  asm volatile("cp.async.wait_group 0;\n")
#define CP_WAIT1()  asm volatile("cp.async.wait_group 1;\n")

// ---------------------------------------------------------------------------
// Kernel 0: split input x into fp16 hi/lo.
// ---------------------------------------------------------------------------
__global__ __launch_bounds__(256) void split_x_kernel(const float* __restrict__ x)
{
    int idx = blockIdx.x * 256 + threadIdx.x;          // one float4 each
    float4 f = ((const float4*)x)[idx];
    __half h0,l0,h1,l1,h2,l2,h3,l3;
    split1(f.x,h0,l0); split1(f.y,h1,l1); split1(f.z,h2,l2); split1(f.w,h3,l3);
    uint2 uh; uh.x = packh(h0,h1); uh.y = packh(h2,h3);
    uint2 ul; ul.x = packh(l0,l1); ul.y = packh(l2,l3);
    *(uint2*)&g_xh[(size_t)idx*4] = uh;
    *(uint2*)&g_xl[(size_t)idx*4] = ul;
}

// ---------------------------------------------------------------------------
// Kernel 1: QKV projection on tensor cores (split-fp16 3-MMA, full accuracy).
// Q -> hi+lo (pre-scaled 1/16); K -> hi only; V -> hi only, transposed.
// ---------------------------------------------------------------------------
#define GSTR 264
#define QKV_SMEM_BYTES ((2*128*GSTR + 2*64*GSTR) * 2)   // 202,752

__global__ __launch_bounds__(256, 1) void qkv_mma_kernel(
    const float* __restrict__ Wq, const float* __restrict__ bq,
    const float* __restrict__ Wk, const float* __restrict__ bk,
    const float* __restrict__ Wv, const float* __restrict__ bv)
{
    const float* W;
    const float* bias;
    if (blockIdx.z == 0)      { W = Wq; bias = bq; }
    else if (blockIdx.z == 1) { W = Wk; bias = bk; }
    else                      { W = Wv; bias = bv; }

    extern __shared__ __half qsm[];
    __half* Xh = qsm;
    __half* Xl = Xh + 128*GSTR;
    __half* Wh = Xl + 128*GSTR;
    __half* Wl = Wh + 64*GSTR;

    const int tid  = threadIdx.x;
    const int lane = tid & 31;
    const int w    = tid >> 5;
    const int g    = lane >> 2;
    const int c    = lane & 3;
    const int wr   = w >> 1;
    const int wc   = w & 1;
    const int m0   = blockIdx.x * 128;
    const int n0   = blockIdx.y * 64;

    const unsigned uXh = (unsigned)__cvta_generic_to_shared(Xh);
    const unsigned uXl = (unsigned)__cvta_generic_to_shared(Xl);
    const unsigned uWh = (unsigned)__cvta_generic_to_shared(Wh);
    const unsigned uWl = (unsigned)__cvta_generic_to_shared(Wl);

    {
        const __half* xh = g_xh + (size_t)m0*DD;
        const __half* xl = g_xl + (size_t)m0*DD;
        #pragma unroll
        for (int t = 0; t < 16; t++) {
            int idx = tid + t*256;
            int row = idx >> 5, ck = idx & 31;
            unsigned doff = (unsigned)(row*GSTR + ck*8) * 2u;
            CP16(uXh + doff, xh + (size_t)row*DD + ck*8);
            CP16(uXl + doff, xl + (size_t)row*DD + ck*8);
        }
        CP_COMMIT();
    }
    #pragma unroll
    for (int i = 0; i < 16; i++) {
        int idx = tid + i*256;
        int row = idx >> 6, c4 = idx & 63;
        float4 f = __ldg((const float4*)&W[(size_t)(n0+row)*DD + c4*4]);
        __half h0,l0,h1,l1,h2,l2,h3,l3;
        split1(f.x,h0,l0); split1(f.y,h1,l1); split1(f.z,h2,l2); split1(f.w,h3,l3);
        unsigned* ph = (unsigned*)&Wh[row*GSTR + c4*4];
        unsigned* pl = (unsigned*)&Wl[row*GSTR + c4*4];
        ph[0] = packh(h0,h1); ph[1] = packh(h2,h3);
        pl[0] = packh(l0,l1); pl[1] = packh(l2,l3);
    }
    CP_WAIT0();
    __syncthreads();

    const int lrow = lane & 7;
    const int p8r  = (lane >> 3) & 1;
    const int p8c  = (lane >> 4) & 1;
    const unsigned aX0 = ((wr*32      + lrow + p8r*8)*GSTR + p8c*8) * 2u;
    const unsigned aX1 = ((wr*32 + 16 + lrow + p8r*8)*GSTR + p8c*8) * 2u;
    const unsigned bW  = ((wc*32      + lrow + p8r*8)*GSTR + p8c*8) * 2u;

    float acc[2][4][4];
    #pragma unroll
    for (int mf = 0; mf < 2; mf++)
        #pragma unroll
        for (int nf = 0; nf < 4; nf++)
            #pragma unroll
            for (int r = 0; r < 4; r++) acc[mf][nf][r] = 0.f;

    #pragma unroll
    for (int ks = 0; ks < 16; ks++) {
        unsigned ah[2][4], al[2][4];
        ldsm4(ah[0], uXh + aX0 + ks*32);
        ldsm4(al[0], uXl + aX0 + ks*32);
        ldsm4(ah[1], uXh + aX1 + ks*32);
        ldsm4(al[1], uXl + aX1 + ks*32);
        #pragma unroll
        for (int p = 0; p < 2; p++) {
            unsigned bh[4], bl[4];
            const unsigned po = (unsigned)(p * 16*GSTR*2);
            ldsm4(bh, uWh + bW + po + ks*32);
            ldsm4(bl, uWl + bW + po + ks*32);
            #pragma unroll
            for (int mf = 0; mf < 2; mf++) {
                mmaf16(acc[mf][2*p],   ah[mf], bh[0], bh[2]);
                mmaf16(acc[mf][2*p],   al[mf], bh[0], bh[2]);
                mmaf16(acc[mf][2*p],   ah[mf], bl[0], bl[2]);
                mmaf16(acc[mf][2*p+1], ah[mf], bh[1], bh[3]);
                mmaf16(acc[mf][2*p+1], al[mf], bh[1], bh[3]);
                mmaf16(acc[mf][2*p+1], ah[mf], bl[1], bl[3]);
            }
        }
    }

    float bb2[4][2];
    #pragma unroll
    for (int nf = 0; nf < 4; nf++) {
        int col = n0 + wc*32 + nf*8 + 2*c;
        bb2[nf][0] = __ldg(&bias[col]);
        bb2[nf][1] = __ldg(&bias[col+1]);
    }

    if (blockIdx.z == 0) {
        // Q: hi + lo, pre-scaled 1/16
        #pragma unroll
        for (int mf = 0; mf < 2; mf++) {
            int r0g = m0 + wr*32 + mf*16 + g;
            #pragma unroll
            for (int nf = 0; nf < 4; nf++) {
                int col = n0 + wc*32 + nf*8 + 2*c;
                float v0 = (acc[mf][nf][0] + bb2[nf][0]) * 0.0625f;
                float v1 = (acc[mf][nf][1] + bb2[nf][1]) * 0.0625f;
                float v2 = (acc[mf][nf][2] + bb2[nf][0]) * 0.0625f;
                float v3 = (acc[mf][nf][3] + bb2[nf][1]) * 0.0625f;
                __half h0,l0,h1,l1;
                split1(v0,h0,l0); split1(v1,h1,l1);
                *(unsigned*)&g_qh[(size_t)r0g*DD + col] = packh(h0,h1);
                *(unsigned*)&g_ql[(size_t)r0g*DD + col] = packh(l0,l1);
                split1(v2,h0,l0); split1(v3,h1,l1);
                *(unsigned*)&g_qh[(size_t)(r0g+8)*DD + col] = packh(h0,h1);
                *(unsigned*)&g_ql[(size_t)(r0g+8)*DD + col] = packh(l0,l1);
            }
        }
    } else if (blockIdx.z == 1) {
        // K: hi only
        #pragma unroll
        for (int mf = 0; mf < 2; mf++) {
            int r0g = m0 + wr*32 + mf*16 + g;
            #pragma unroll
            for (int nf = 0; nf < 4; nf++) {
                int col = n0 + wc*32 + nf*8 + 2*c;
                float v0 = acc[mf][nf][0] + bb2[nf][0];
                float v1 = acc[mf][nf][1] + bb2[nf][1];
                float v2 = acc[mf][nf][2] + bb2[nf][0];
                float v3 = acc[mf][nf][3] + bb2[nf][1];
                *(unsigned*)&g_kh[(size_t)r0g*DD + col] =
                    packh(__float2half_rn(v0), __float2half_rn(v1));
                *(unsigned*)&g_kh[(size_t)(r0g+8)*DD + col] =
                    packh(__float2half_rn(v2), __float2half_rn(v3));
            }
        }
    } else {
        // V: hi only, transposed through smem, coalesced stores
        __syncthreads();
        __half* Th = qsm;          // [64 d][136 s]
        #pragma unroll
        for (int mf = 0; mf < 2; mf++) {
            int s0 = wr*32 + mf*16 + g;
            #pragma unroll
            for (int nf = 0; nf < 4; nf++) {
                int d0 = wc*32 + nf*8 + 2*c;
                Th[d0*136 + s0]       = __float2half_rn(acc[mf][nf][0] + bb2[nf][0]);
                Th[(d0+1)*136 + s0]   = __float2half_rn(acc[mf][nf][1] + bb2[nf][1]);
                Th[d0*136 + s0+8]     = __float2half_rn(acc[mf][nf][2] + bb2[nf][0]);
                Th[(d0+1)*136 + s0+8] = __float2half_rn(acc[mf][nf][3] + bb2[nf][1]);
            }
        }
        __syncthreads();
        const int bbat = m0 >> 12;
        const int sbase = m0 & (SS-1);
        #pragma unroll
        for (int t = 0; t < 4; t++) {
            int idx = tid + t*256;
            int d = idx >> 4, ch = idx & 15;
            uint4 vh = *(uint4*)&Th[d*136 + ch*8];
            size_t off = ((size_t)(bbat*DD + n0 + d))*SS + sbase + ch*8;
            *(uint4*)&g_vth[off] = vh;
        }
    }
}

// ---------------------------------------------------------------------------
// Kernel 2: flash attention, 2-MMA A-side-corrected split, double-buffered K/V.
// S = (Qh+Ql)·Kh (exact in Q); O = (Ph+Pl)·Vh (exact in P).
// ---------------------------------------------------------------------------
#define QSTR 264
#define VSTR 72
#define PSTR 72
// Qh,Ql,Kh0,Kh1: 4*64*264*2 + Vth0,Vth1: 2*256*72*2 + Ph,Pl: 2*64*72*2 + red 1024
#define ATTN_SMEM_BYTES 228352

__global__ __launch_bounds__(256, 1) void attn_kernel(float* __restrict__ out)
{
    extern __shared__ __half sm[];
    __half* Qh   = sm;
    __half* Ql   = Qh   + 64*QSTR;
    __half* Kh0  = Ql   + 64*QSTR;
    __half* Kh1  = Kh0  + 64*QSTR;
    __half* Vth0 = Kh1  + 64*QSTR;
    __half* Vth1 = Vth0 + 256*VSTR;
    __half* Ph   = Vth1 + 256*VSTR;
    __half* Pl   = Ph   + 64*PSTR;
    float* redm = (float*)(Pl + 64*PSTR);   // [2][64]
    float* reds = redm + 128;               // [2][64]

    const int tid  = threadIdx.x;
    const int lane = tid & 31;
    const int w    = tid >> 5;
    const int g    = lane >> 2;
    const int c    = lane & 3;
    const int wr   = w >> 1;
    const int wc   = w & 1;
    const int b    = blockIdx.y;
    const int q0   = blockIdx.x * BQ;
    const int r0   = wr*16 + g;
    const int r1   = r0 + 8;

    const unsigned uQh = (unsigned)__cvta_generic_to_shared(Qh);
    const unsigned uQl = (unsigned)__cvta_generic_to_shared(Ql);
    unsigned uK[2], uV[2];
    uK[0] = (unsigned)__cvta_generic_to_shared(Kh0);
    uK[1] = (unsigned)__cvta_generic_to_shared(Kh1);
    uV[0] = (unsigned)__cvta_generic_to_shared(Vth0);
    uV[1] = (unsigned)__cvta_generic_to_shared(Vth1);
    const unsigned uPh = (unsigned)__cvta_generic_to_shared(Ph);
    const unsigned uPl = (unsigned)__cvta_generic_to_shared(Pl);

    const __half* khg0 = g_kh + (size_t)b*SS*DD;
    const __half* vhg0 = g_vth + (size_t)b*DD*SS;

    // ---- prologue: Q(hi,lo) + K0 + V0 into buffer 0, one group ----
    {
        const __half* qhg = g_qh + ((size_t)b*SS + q0)*DD;
        const __half* qlg = g_ql + ((size_t)b*SS + q0)*DD;
        #pragma unroll
        for (int t = 0; t < 8; t++) {
            int idx = tid + t*256;
            int row = idx >> 5, ck = idx & 31;
            unsigned doff = (unsigned)(row*QSTR + ck*8) * 2u;
            CP16(uQh + doff, qhg + row*DD + ck*8);
            CP16(uQl + doff, qlg + row*DD + ck*8);
            CP16(uK[0] + doff, khg0 + (size_t)row*DD + ck*8);
            int vd = idx >> 3, vk = idx & 7;
            CP16(uV[0] + (unsigned)(vd*VSTR + vk*8)*2u,
                 vhg0 + (size_t)vd*SS + vk*8);
        }
        CP_COMMIT();
    }

    const int lrow = lane & 7;
    const int p8r  = (lane >> 3) & 1;
    const int p8c  = (lane >> 4) & 1;
    const unsigned aQ = ((wr*16  + lrow + p8r*8)*QSTR + p8c*8) * 2u;
    const unsigned oK = ((wc*32  + lrow + p8r*8)*QSTR + p8c*8) * 2u;
    const unsigned aP = ((wr*16  + lrow + p8r*8)*PSTR + p8c*8) * 2u;
    const unsigned oV = ((wc*128 + lrow + p8r*8)*VSTR + p8c*8) * 2u;

    float m0 = -INFINITY, m1 = -INFINITY, lsum0 = 0.f, lsum1 = 0.f;
    float O[16][4];
    #pragma unroll
    for (int nf = 0; nf < 16; nf++)
        #pragma unroll
        for (int r = 0; r < 4; r++) O[nf][r] = 0.f;

    int cur = 0;
    for (int jt = 0; jt < SS; jt += BK, cur ^= 1) {
        __syncthreads();   // prev iter's compute done -> buf[cur^1] reusable

        if (jt + BK < SS) {
            // prefetch tile j+1 into the other buffer
            const __half* khg = khg0 + (size_t)(jt+BK)*DD;
            const unsigned dK = uK[cur^1], dV = uV[cur^1];
            #pragma unroll
            for (int t = 0; t < 8; t++) {
                int idx = tid + t*256;
                int row = idx >> 5, ck = idx & 31;
                CP16(dK + (unsigned)(row*QSTR + ck*8)*2u, khg + row*DD + ck*8);
                int vd = idx >> 3, vk = idx & 7;
                CP16(dV + (unsigned)(vd*VSTR + vk*8)*2u,
                     vhg0 + (size_t)vd*SS + (jt+BK) + vk*8);
            }
            CP_COMMIT();
            CP_WAIT1();    // tile j (second-newest group) complete
        } else {
            CP_WAIT0();
        }
        __syncthreads();   // tile j visible block-wide

        const unsigned uKc = uK[cur] + oK;
        const unsigned uVc = uV[cur] + oV;

        // ---- S = Q K_hi^T (warp 16x32), 2-MMA ----
        float S[4][4];
        #pragma unroll
        for (int nf = 0; nf < 4; nf++)
            #pragma unroll
            for (int r = 0; r < 4; r++) S[nf][r] = 0.f;

        #pragma unroll
        for (int ks = 0; ks < 16; ks++) {
            unsigned ah[4], al[4];
            ldsm4(ah, uQh + aQ + ks*32);
            ldsm4(al, uQl + aQ + ks*32);
            #pragma unroll
            for (int p = 0; p < 2; p++) {
                unsigned bh[4];
                ldsm4(bh, uKc + (unsigned)(p * 16*QSTR*2) + ks*32);
                mmaf16(S[2*p],   ah, bh[0], bh[2]);
                mmaf16(S[2*p],   al, bh[0], bh[2]);
                mmaf16(S[2*p+1], ah, bh[1], bh[3]);
                mmaf16(S[2*p+1], al, bh[1], bh[3]);
            }
        }

        // ---- online softmax ----
        float rm0 = -INFINITY, rm1 = -INFINITY;
        #pragma unroll
        for (int nf = 0; nf < 4; nf++) {
            rm0 = fmaxf(rm0, fmaxf(S[nf][0], S[nf][1]));
            rm1 = fmaxf(rm1, fmaxf(S[nf][2], S[nf][3]));
        }
        rm0 = fmaxf(rm0, __shfl_xor_sync(0xffffffffu, rm0, 1));
        rm0 = fmaxf(rm0, __shfl_xor_sync(0xffffffffu, rm0, 2));
        rm1 = fmaxf(rm1, __shfl_xor_sync(0xffffffffu, rm1, 1));
        rm1 = fmaxf(rm1, __shfl_xor_sync(0xffffffffu, rm1, 2));
        if (c == 0) {
            redm[wc*64 + r0] = rm0;
            redm[wc*64 + r1] = rm1;
        }
        __syncthreads();

        float mn0 = fmaxf(m0, fmaxf(redm[r0], redm[64 + r0]));
        float mn1 = fmaxf(m1, fmaxf(redm[r1], redm[64 + r1]));

        float ps0 = 0.f, ps1 = 0.f;
        #pragma unroll
        for (int nf = 0; nf < 4; nf++) {
            float p0 = __expf(S[nf][0] - mn0);
            float p1 = __expf(S[nf][1] - mn0);
            float p2 = __expf(S[nf][2] - mn1);
            float p3 = __expf(S[nf][3] - mn1);
            ps0 += p0 + p1;
            ps1 += p2 + p3;
            const int col = wc*32 + nf*8 + 2*c;
            __half h0, l0, h1, l1;
            split1(p0, h0, l0); split1(p1, h1, l1);
            *(unsigned*)&Ph[r0*PSTR + col] = packh(h0, h1);
            *(unsigned*)&Pl[r0*PSTR + col] = packh(l0, l1);
            split1(p2, h0, l0); split1(p3, h1, l1);
            *(unsigned*)&Ph[r1*PSTR + col] = packh(h0, h1);
            *(unsigned*)&Pl[r1*PSTR + col] = packh(l0, l1);
        }
        ps0 += __shfl_xor_sync(0xffffffffu, ps0, 1);
        ps0 += __shfl_xor_sync(0xffffffffu, ps0, 2);
        ps1 += __shfl_xor_sync(0xffffffffu, ps1, 1);
        ps1 += __shfl_xor_sync(0xffffffffu, ps1, 2);
        if (c == 0) {
            reds[wc*64 + r0] = ps0;
            reds[wc*64 + r1] = ps1;
        }
        __syncthreads();   // reds + P visible

        float a0f = __expf(m0 - mn0);
        float a1f = __expf(m1 - mn1);
        lsum0 = lsum0*a0f + reds[r0] + reds[64 + r0];
        lsum1 = lsum1*a1f + reds[r1] + reds[64 + r1];
        m0 = mn0; m1 = mn1;
        #pragma unroll
        for (int nf = 0; nf < 16; nf++) {
            O[nf][0] *= a0f; O[nf][1] *= a0f;
            O[nf][2] *= a1f; O[nf][3] *= a1f;
        }

        // ---- O += P V_hi (warp 16x128), 2-MMA ----
        #pragma unroll
        for (int kk = 0; kk < 4; kk++) {
            unsigned ah[4], al[4];
            ldsm4(ah, uPh + aP + kk*32);
            ldsm4(al, uPl + aP + kk*32);
            #pragma unroll
            for (int p = 0; p < 8; p++) {
                unsigned bh[4];
                ldsm4(bh, uVc + (unsigned)(p * 16*VSTR*2) + kk*32);
                mmaf16(O[2*p],   ah, bh[0], bh[2]);
                mmaf16(O[2*p],   al, bh[0], bh[2]);
                mmaf16(O[2*p+1], ah, bh[1], bh[3]);
                mmaf16(O[2*p+1], al, bh[1], bh[3]);
            }
        }
    }

    // ---- normalize + store ----
    const float inv0 = 1.0f / lsum0;
    const float inv1 = 1.0f / lsum1;
    #pragma unroll
    for (int nf = 0; nf < 16; nf++) {
        const int col = wc*128 + nf*8 + 2*c;
        float2 o0, o1;
        o0.x = O[nf][0]*inv0; o0.y = O[nf][1]*inv0;
        o1.x = O[nf][2]*inv1; o1.y = O[nf][3]*inv1;
        *(float2*)&out[((size_t)b*SS + q0 + r0)*DD + col] = o0;
        *(float2*)&out[((size_t)b*SS + q0 + r1)*DD + col] = o1;
    }
}

// ---------------------------------------------------------------------------
// Launch
// ---------------------------------------------------------------------------
extern "C" void kernel_launch(void* const* d_in, const int* in_sizes, int n_in,
                              void* d_out, int out_size)
{
    (void)in_sizes; (void)n_in; (void)out_size;
    const float* x  = (const float*)d_in[0];
    const float* Wq = (const float*)d_in[1];
    const float* bq = (const float*)d_in[2];
    const float* Wk = (const float*)d_in[3];
    const float* bk = (const float*)d_in[4];
    const float* Wv = (const float*)d_in[5];
    const float* bv = (const float*)d_in[6];
    float* out = (float*)d_out;

    split_x_kernel<<<(BB*SS*DD)/(4*256), 256>>>(x);

    cudaFuncSetAttribute(qkv_mma_kernel, cudaFuncAttributeMaxDynamicSharedMemorySize,
                         QKV_SMEM_BYTES);
    dim3 grid_qkv((BB*SS)/128, DD/64, 3);
    qkv_mma_kernel<<<grid_qkv, 256, QKV_SMEM_BYTES>>>(Wq, bq, Wk, bk, Wv, bv);

    cudaFuncSetAttribute(attn_kernel, cudaFuncAttributeMaxDynamicSharedMemorySize,
                         ATTN_SMEM_BYTES);
    dim3 grid_attn(SS/BQ, BB);
    attn_kernel<<<grid_attn, 256, ATTN_SMEM_BYTES>>>(out);
}